// round 12
// baseline (speedup 1.0000x reference)
#include <cuda_runtime.h>
#include <cuda_bf16.h>
#include <math.h>
#include <stdint.h>

#define LSEQ 4096
#define NHQ 8
#define NKV 4
#define DH 256
#define HID 2304
#define WIN 2048
#define QDIM (NHQ*DH)   /* 2048 */
#define KDIM (NKV*DH)   /* 1024 */
#define QKVN (QDIM + 2*KDIM)  /* 4096 fused N */

#define SCALEF 0.05892556509887896f   /* 288^-0.5 */
#define NEGC  (-1.0e9f)

// fused QKV projection output (rows = l - WIN, cols = [q|k|v])
static __device__ float g_qkv[(size_t)WIN * QKVN];
static __device__ float g_vmean[KDIM];
static __device__ float g_lowrow[HID];
static __device__ float g_invf[128];
static __device__ float g_xpart[16 * HID];
static __device__ float g_xsum[HID];
static __device__ float g_vpart[8 * KDIM];
static __device__ float g_lowpart[8 * HID];

// bf16-split operands
static __device__ __nv_bfloat16 g_xhi[(size_t)LSEQ * HID];
static __device__ __nv_bfloat16 g_xlo[(size_t)LSEQ * HID];
static __device__ __nv_bfloat16 g_ahi[(size_t)WIN * QDIM];
static __device__ __nv_bfloat16 g_alo[(size_t)WIN * QDIM];
// roped, compacted (rows = l - WIN)
static __device__ __nv_bfloat16 g_qhi[(size_t)WIN * QDIM];
static __device__ __nv_bfloat16 g_qlo[(size_t)WIN * QDIM];
static __device__ __nv_bfloat16 g_khi[(size_t)WIN * KDIM];
static __device__ __nv_bfloat16 g_klo[(size_t)WIN * KDIM];
// V transposed per kv head: [hkv][d=256][k-WIN=2048]
static __device__ __nv_bfloat16 g_vthi[(size_t)NKV * DH * WIN];
static __device__ __nv_bfloat16 g_vtlo[(size_t)NKV * DH * WIN];
// weights transposed to [N][K] K-major; qkv fused [4096][2304]
static __device__ __nv_bfloat16 g_wqkvhi[(size_t)QKVN * HID];
static __device__ __nv_bfloat16 g_wqkvlo[(size_t)QKVN * HID];
static __device__ __nv_bfloat16 g_wohi[(size_t)HID * QDIM];
static __device__ __nv_bfloat16 g_wolo[(size_t)HID * QDIM];

// ===========================================================================
// Helpers (base-target PTX only)
// ===========================================================================
__device__ __forceinline__ uint32_t smem_u32(const void* p) {
    uint32_t r;
    asm("{ .reg .u64 t; cvta.to.shared.u64 t, %1; cvt.u32.u64 %0, t; }"
        : "=r"(r) : "l"(p));
    return r;
}

#define CP_ASYNC16(dst, src) \
    asm volatile("cp.async.cg.shared.global [%0], [%1], 16;" \
                 :: "r"(dst), "l"(src) : "memory")
#define CP_COMMIT()  asm volatile("cp.async.commit_group;" ::: "memory")
#define CP_WAIT0()   asm volatile("cp.async.wait_group 0;" ::: "memory")
#define CP_WAIT1()   asm volatile("cp.async.wait_group 1;" ::: "memory")

#define LDSM4(R, addr) \
    asm volatile("ldmatrix.sync.aligned.m8n8.x4.shared.b16 {%0,%1,%2,%3}, [%4];" \
        : "=r"((R)[0]), "=r"((R)[1]), "=r"((R)[2]), "=r"((R)[3]) : "r"(addr))

#define MMA_BF16(ACC, A, B) \
    asm volatile("mma.sync.aligned.m16n8k16.row.col.f32.bf16.bf16.f32 " \
        "{%0,%1,%2,%3}, {%4,%5,%6,%7}, {%8,%9}, {%0,%1,%2,%3};" \
        : "+f"((ACC)[0]), "+f"((ACC)[1]), "+f"((ACC)[2]), "+f"((ACC)[3]) \
        : "r"((A)[0]), "r"((A)[1]), "r"((A)[2]), "r"((A)[3]), \
          "r"((B)[0]), "r"((B)[1]))

// ===========================================================================
// bf16-split MMA GEMM, CTA tile 128x256, warp tile 64x64 (2m x 4n warps),
// BK=32, double-buffered cp.async. 6 MMA per LDSM (vs 4 in the 128x128
// version) to relieve the smem-read bound seen in ncu (tensor=46%).
// Stage layout (bytes): Ahi@0 (128x80), Alo@10240, Bhi@20480 (256x80),
// Blo@40960; stage stride 61440, 2 stages = 122880 B dynamic smem.
// ===========================================================================
__global__ __launch_bounds__(256, 1) void gemm_mma(
    const __nv_bfloat16* __restrict__ Ahi, const __nv_bfloat16* __restrict__ Alo,
    const __nv_bfloat16* __restrict__ Bhi, const __nv_bfloat16* __restrict__ Blo,
    float* __restrict__ C, int M, int N, int K)
{
    extern __shared__ char smdyn[];
    const uint32_t sbase = smem_u32(smdyn);
    const int tid  = threadIdx.x;
    const int warp = tid >> 5;
    const int lane = tid & 31;
    const int wm = warp >> 2;            // 0..1
    const int wn = warp & 3;             // 0..3
    const int row0 = blockIdx.y * 128;
    const int col0 = blockIdx.x * 256;

    const __nv_bfloat16* gsrc[4] = {
        Ahi + (size_t)row0 * K, Alo + (size_t)row0 * K,
        Bhi + (size_t)col0 * K, Blo + (size_t)col0 * K };

    float acc[4][8][4];
#pragma unroll
    for (int a = 0; a < 4; a++)
#pragma unroll
        for (int b = 0; b < 8; b++)
#pragma unroll
            for (int c = 0; c < 4; c++) acc[a][b][c] = 0.0f;

    const int S = K >> 5;

    // copy one K-slab (3072 16B-chunks = 12 iters x 256 threads)
#define GEMM_COPY_SLAB(stoff, k0)                                            \
    do {                                                                     \
        _Pragma("unroll")                                                    \
        for (int i = 0; i < 12; i++) {                                       \
            int c = tid + (i << 8);                                          \
            int op, row, dsto;                                               \
            if (c < 512)       { op = 0; row = c;          dsto = 0; }       \
            else if (c < 1024) { op = 1; row = c - 512;    dsto = 10240; }   \
            else if (c < 2048) { op = 2; row = c - 1024;   dsto = 20480; }   \
            else               { op = 3; row = c - 2048;   dsto = 40960; }   \
            int kc = row & 3; row >>= 2;                                     \
            uint32_t dst = sbase + (uint32_t)(stoff) +                       \
                           (uint32_t)(dsto + row * 80 + kc * 16);            \
            const char* src = (const char*)(gsrc[op] + (size_t)row * K + (k0)) + kc * 16; \
            CP_ASYNC16(dst, src);                                            \
        }                                                                    \
    } while (0)

    GEMM_COPY_SLAB(0, 0);
    CP_COMMIT();
    CP_WAIT0();
    __syncthreads();

    for (int s = 0; s < S; s++) {
        const int st = s & 1;
        if (s + 1 < S) {
            GEMM_COPY_SLAB((st ^ 1) * 61440, (s + 1) << 5);
            CP_COMMIT();
        }

        const uint32_t base = sbase + (uint32_t)(st * 61440);
#pragma unroll
        for (int t = 0; t < 2; t++) {
            uint32_t ah[4][4], al[4][4];
#pragma unroll
            for (int mf = 0; mf < 4; mf++) {
                uint32_t ad = base + (uint32_t)((wm * 64 + mf * 16 + (lane & 15)) * 80
                               + t * 32 + ((lane >> 4) << 4));
                LDSM4(ah[mf], ad);
                LDSM4(al[mf], ad + 10240);
            }
#pragma unroll
            for (int ng = 0; ng < 4; ng++) {
                uint32_t bd = base + 20480u +
                    (uint32_t)((wn * 64 + ng * 16 + (lane & 15)) * 80
                               + t * 32 + ((lane >> 4) << 4));
                uint32_t h4[4], l4[4];
                LDSM4(h4, bd);
                LDSM4(l4, bd + 20480);
                uint32_t bh0[2] = {h4[0], h4[2]}, bh1[2] = {h4[1], h4[3]};
                uint32_t bl0[2] = {l4[0], l4[2]}, bl1[2] = {l4[1], l4[3]};
#pragma unroll
                for (int mf = 0; mf < 4; mf++) {
                    MMA_BF16(acc[mf][2 * ng],     ah[mf], bh0);
                    MMA_BF16(acc[mf][2 * ng],     ah[mf], bl0);
                    MMA_BF16(acc[mf][2 * ng],     al[mf], bh0);
                    MMA_BF16(acc[mf][2 * ng + 1], ah[mf], bh1);
                    MMA_BF16(acc[mf][2 * ng + 1], ah[mf], bl1);
                    MMA_BF16(acc[mf][2 * ng + 1], al[mf], bh1);
                }
            }
        }
        CP_WAIT0();
        __syncthreads();
    }

    const int qr = lane >> 2;
    const int qc = (lane & 3) * 2;
#pragma unroll
    for (int mf = 0; mf < 4; mf++)
#pragma unroll
        for (int nf = 0; nf < 8; nf++) {
            int r = row0 + wm * 64 + mf * 16 + qr;
            int cI = col0 + wn * 64 + nf * 8 + qc;
            float2 v0 = make_float2(acc[mf][nf][0], acc[mf][nf][1]);
            float2 v1 = make_float2(acc[mf][nf][2], acc[mf][nf][3]);
            *(float2*)(C + (size_t)r * N + cI)       = v0;
            *(float2*)(C + (size_t)(r + 8) * N + cI) = v1;
        }
}

// ===========================================================================
// bf16 split conversions
// ===========================================================================
__global__ void split_kernel(const float* __restrict__ src,
                             __nv_bfloat16* __restrict__ hi,
                             __nv_bfloat16* __restrict__ lo, int n4)
{
    int i = blockIdx.x * blockDim.x + threadIdx.x;
    if (i >= n4) return;
    float4 v = *(const float4*)(src + (size_t)i * 4);
    float f[4] = {v.x, v.y, v.z, v.w};
    __nv_bfloat16 h[4], l[4];
#pragma unroll
    for (int j = 0; j < 4; j++) {
        h[j] = __float2bfloat16(f[j]);
        l[j] = __float2bfloat16(f[j] - __bfloat162float(h[j]));
    }
    *(__nv_bfloat162*)(hi + (size_t)i * 4)     = __nv_bfloat162(h[0], h[1]);
    *(__nv_bfloat162*)(hi + (size_t)i * 4 + 2) = __nv_bfloat162(h[2], h[3]);
    *(__nv_bfloat162*)(lo + (size_t)i * 4)     = __nv_bfloat162(l[0], l[1]);
    *(__nv_bfloat162*)(lo + (size_t)i * 4 + 2) = __nv_bfloat162(l[2], l[3]);
}

// Fused transposing split of wq|wk|wv into g_wqkv [4096][2304]
__global__ void splitT_qkv_kernel(const float* __restrict__ wq,
                                  const float* __restrict__ wk,
                                  const float* __restrict__ wv)
{
    __shared__ float t[32][33];
    const int n0 = blockIdx.x * 32;
    const int k0 = blockIdx.y * 32;
    const int tx = threadIdx.x, ty = threadIdx.y;

    const float* W;
    int Nsrc, nb;
    if (n0 < QDIM)             { W = wq; Nsrc = QDIM; nb = n0; }
    else if (n0 < QDIM + KDIM) { W = wk; Nsrc = KDIM; nb = n0 - QDIM; }
    else                       { W = wv; Nsrc = KDIM; nb = n0 - QDIM - KDIM; }

#pragma unroll
    for (int j = 0; j < 4; j++)
        t[ty + j * 8][tx] = W[(size_t)(k0 + ty + j * 8) * Nsrc + nb + tx];
    __syncthreads();
#pragma unroll
    for (int j = 0; j < 4; j++) {
        float v = t[tx][ty + j * 8];
        __nv_bfloat16 h = __float2bfloat16(v);
        __nv_bfloat16 l = __float2bfloat16(v - __bfloat162float(h));
        size_t o = (size_t)(n0 + ty + j * 8) * HID + k0 + tx;
        g_wqkvhi[o] = h;
        g_wqkvlo[o] = l;
    }
}

__global__ void splitT_kernel(const float* __restrict__ W,
                              __nv_bfloat16* __restrict__ hi,
                              __nv_bfloat16* __restrict__ lo, int K, int N)
{
    __shared__ float t[32][33];
    const int n0 = blockIdx.x * 32;
    const int k0 = blockIdx.y * 32;
    const int tx = threadIdx.x, ty = threadIdx.y;
#pragma unroll
    for (int j = 0; j < 4; j++)
        t[ty + j * 8][tx] = W[(size_t)(k0 + ty + j * 8) * N + n0 + tx];
    __syncthreads();
#pragma unroll
    for (int j = 0; j < 4; j++) {
        float v = t[tx][ty + j * 8];
        __nv_bfloat16 h = __float2bfloat16(v);
        __nv_bfloat16 l = __float2bfloat16(v - __bfloat162float(h));
        size_t o = (size_t)(n0 + ty + j * 8) * K + k0 + tx;
        hi[o] = h;
        lo[o] = l;
    }
}

// ===========================================================================
// RoPE: invf table once, trig inline (double range-reduction + __sincosf)
// ===========================================================================
__global__ void invf_init_kernel()
{
    int i = threadIdx.x;
    double ex = (double)(2 * i) / 256.0;
    float pf = (float)pow(10000.0, ex);
    g_invf[i] = __fdiv_rn(1.0f, pf);
}

__global__ void rope_split_kernel(int coloff, int nheads,
                                  __nv_bfloat16* __restrict__ hi,
                                  __nv_bfloat16* __restrict__ lo)
{
    int row = blockIdx.x;
    int l = WIN + row;
    int i = threadIdx.x;
    float ang = (float)l * g_invf[i];
    double a  = (double)ang;
    double kq = rint(a * 0.15915494309189535);
    double r  = fma(-kq, 6.283185307179586, a);
    float s, c;
    __sincosf((float)r, &s, &c);
    int nd = nheads * DH;
    for (int h = 0; h < nheads; h++) {
        size_t base = (size_t)row * QKVN + coloff + (size_t)h * DH;
        float x1 = g_qkv[base + i];
        float x2 = g_qkv[base + i + 128];
        float y1 = x1 * c - x2 * s;
        float y2 = x2 * c + x1 * s;
        size_t o = (size_t)row * nd + (size_t)h * DH;
        __nv_bfloat16 h1 = __float2bfloat16(y1);
        __nv_bfloat16 h2 = __float2bfloat16(y2);
        hi[o + i]       = h1;
        hi[o + i + 128] = h2;
        lo[o + i]       = __float2bfloat16(y1 - __bfloat162float(h1));
        lo[o + i + 128] = __float2bfloat16(y2 - __bfloat162float(h2));
    }
}

// V transpose-split from g_qkv cols [3072..4096) -> Vt[hkv][d][k] bf16 hi/lo
__global__ void vt_split_kernel()
{
    __shared__ float t[32][33];
    const int k0  = blockIdx.x * 32;
    const int d0  = blockIdx.y * 32;
    const int hkv = blockIdx.z;
    const int tx = threadIdx.x, ty = threadIdx.y;
#pragma unroll
    for (int j = 0; j < 4; j++)
        t[ty + j * 8][tx] = g_qkv[(size_t)(k0 + ty + j * 8) * QKVN
                                  + QDIM + KDIM + hkv * DH + d0 + tx];
    __syncthreads();
#pragma unroll
    for (int j = 0; j < 4; j++) {
        float v = t[tx][ty + j * 8];
        __nv_bfloat16 h = __float2bfloat16(v);
        __nv_bfloat16 l = __float2bfloat16(v - __bfloat162float(h));
        size_t o = (size_t)hkv * DH * WIN + (size_t)(d0 + ty + j * 8) * WIN + k0 + tx;
        g_vthi[o] = h;
        g_vtlo[o] = l;
    }
}

// ===========================================================================
// lowq path via linearity: vmean = (sum_l x_l) @ wv / 4096
// ===========================================================================
__global__ void xsum_part_kernel(const float* __restrict__ x)
{
    int j = blockIdx.x * 256 + threadIdx.x;
    if (j >= HID) return;
    int p = blockIdx.y;
    float s = 0.0f;
    for (int l = p * 256; l < (p + 1) * 256; l++)
        s += x[(size_t)l * HID + j];
    g_xpart[p * HID + j] = s;
}
__global__ void xsum_comb_kernel()
{
    int j = blockIdx.x * 256 + threadIdx.x;
    if (j >= HID) return;
    float s = 0.0f;
#pragma unroll
    for (int p = 0; p < 16; p++) s += g_xpart[p * HID + j];
    g_xsum[j] = s;
}
__global__ void vmean_part_kernel(const float* __restrict__ wv)
{
    int d = blockIdx.x * 256 + threadIdx.x;
    if (d >= KDIM) return;
    int p = blockIdx.y;
    float s = 0.0f;
    for (int i = p * 288; i < (p + 1) * 288; i++)
        s = fmaf(g_xsum[i], wv[(size_t)i * KDIM + d], s);
    g_vpart[p * KDIM + d] = s;
}
__global__ void vmean_comb_kernel()
{
    int d = blockIdx.x * 256 + threadIdx.x;
    if (d >= KDIM) return;
    float s = 0.0f;
#pragma unroll
    for (int p = 0; p < 8; p++) s += g_vpart[p * KDIM + d];
    g_vmean[d] = s * (1.0f / 4096.0f);
}
__global__ void lowout_part_kernel(const float* __restrict__ wo)
{
    int j = blockIdx.x * 256 + threadIdx.x;
    if (j >= HID) return;
    int p = blockIdx.y;
    float s = 0.0f;
    for (int i = p * 256; i < (p + 1) * 256; i++) {
        int h = i >> 8, d = i & 255;
        float r = g_vmean[(h >> 1) * 256 + d];
        s = fmaf(r, wo[(size_t)i * HID + j], s);
    }
    g_lowpart[p * HID + j] = s;
}
__global__ void lowout_comb_kernel()
{
    int j = blockIdx.x * 256 + threadIdx.x;
    if (j >= HID) return;
    float s = 0.0f;
#pragma unroll
    for (int p = 0; p < 8; p++) s += g_lowpart[p * HID + j];
    g_lowrow[j] = s;
}
__global__ void lowfill_kernel(float* __restrict__ out)
{
    int idx = blockIdx.x * blockDim.x + threadIdx.x;
    if (idx >= WIN * HID) return;
    out[idx] = g_lowrow[idx % HID];
}

// ===========================================================================
// Fast accurate softcap: tanh via MUFU-backed __expf (~2^-22 rel err)
// ===========================================================================
__device__ __forceinline__ float softcap50(float s)
{
    float x = __fdiv_rn(s * SCALEF, 50.0f);
    x = fminf(fmaxf(x, -15.0f), 15.0f);
    float e = __expf(2.0f * x);
    return 50.0f * __fdiv_rn(e - 1.0f, e + 1.0f);
}

// ===========================================================================
// Tensor-core flash attention (q >= 2048), pipelined (validated R10/R11).
// ===========================================================================
__global__ __launch_bounds__(256) void flash_mma(
    const __nv_bfloat16* __restrict__ Qhi, const __nv_bfloat16* __restrict__ Qlo,
    const __nv_bfloat16* __restrict__ Khi, const __nv_bfloat16* __restrict__ Klo,
    const __nv_bfloat16* __restrict__ Vthi, const __nv_bfloat16* __restrict__ Vtlo,
    __nv_bfloat16* __restrict__ Ohi, __nv_bfloat16* __restrict__ Olo)
{
    extern __shared__ char dsm[];
    const uint32_t sb = smem_u32(dsm);
    float* SS  = (float*)(dsm + 183296);
    float* m_s = (float*)(dsm + 202752);
    float* l_s = (float*)(dsm + 203008);
    float* c_s = (float*)(dsm + 203264);

    const int tid  = threadIdx.x;
    const int warp = tid >> 5;
    const int lane = tid & 31;
    const int h    = blockIdx.y;
    const int hkv  = h >> 1;
    const int it   = 31 - (int)blockIdx.x;
    const int q0r  = it * 64;
    const int nk   = 2 * it + 2;

    const size_t vtbase_g = (size_t)hkv * DH * WIN;

#pragma unroll
    for (int i = 0; i < 16; i++) {
        int c = tid + (i << 8);
        int op = c >> 11, cc = c & 2047;
        int row = cc >> 5, ch = cc & 31;
        uint32_t dst = sb + (uint32_t)(op * 33792 + row * 528 + ch * 16);
        const char* src = (const char*)((op ? Qlo : Qhi)
                          + (size_t)(q0r + row) * QDIM + h * DH) + ch * 16;
        CP_ASYNC16(dst, src);
    }
#pragma unroll
    for (int i = 0; i < 8; i++) {
        int c = tid + (i << 8);
        int op = c >> 10, cc = c & 1023;
        int row = cc >> 5, ch = cc & 31;
        uint32_t dst = sb + 67584u + (uint32_t)(op * 16896 + row * 528 + ch * 16);
        const char* src = (const char*)((op ? Klo : Khi)
                          + (size_t)row * KDIM + hkv * DH) + ch * 16;
        CP_ASYNC16(dst, src);
    }
#pragma unroll
    for (int i = 0; i < 8; i++) {
        int c = tid + (i << 8);
        int op = c >> 10, cc = c & 1023;
        int row = cc >> 2, ch = cc & 3;
        uint32_t dst = sb + 101376u + (uint32_t)(op * 20480 + row * 80 + ch * 16);
        const char* src = (const char*)((op ? Vtlo : Vthi)
                          + vtbase_g + (size_t)row * WIN) + ch * 16;
        CP_ASYNC16(dst, src);
    }
    CP_COMMIT();

    if (tid < 64) { m_s[tid] = -INFINITY; l_s[tid] = 0.0f; }

    float o[4][4][4];
#pragma unroll
    for (int a = 0; a < 4; a++)
#pragma unroll
        for (int b = 0; b < 4; b++)
#pragma unroll
            for (int c = 0; c < 4; c++) o[a][b][c] = 0.0f;

    const int wm = warp >> 1;
    const int wn = warp & 1;
    const int qr = lane >> 2, qc = (lane & 3) * 2;

    for (int t = 0; t < nk; t++) {
        if (t + 1 < nk) {
            const int k1 = (t + 1) * 32;
            const uint32_t vtoff = 101376u + (uint32_t)(((t + 1) & 1) * 40960);
#pragma unroll
            for (int i = 0; i < 8; i++) {
                int c = tid + (i << 8);
                int op = c >> 10, cc = c & 1023;
                int row = cc >> 2, ch = cc & 3;
                uint32_t dst = sb + vtoff + (uint32_t)(op * 20480 + row * 80 + ch * 16);
                const char* src = (const char*)((op ? Vtlo : Vthi)
                                  + vtbase_g + (size_t)row * WIN + k1) + ch * 16;
                CP_ASYNC16(dst, src);
            }
            CP_COMMIT();
            CP_WAIT1();
        } else {
            CP_WAIT0();
        }
        __syncthreads();

        const int k0r = t * 32;

        float s[2][4];
#pragma unroll
        for (int nf = 0; nf < 2; nf++)
#pragma unroll
            for (int e = 0; e < 4; e++) s[nf][e] = 0.0f;

#pragma unroll
        for (int ds = 0; ds < 16; ds++) {
            uint32_t ah[4], al[4], kh4[4], kl4[4];
            uint32_t qa = sb + (uint32_t)((wm * 16 + (lane & 15)) * 528
                           + ds * 32 + ((lane >> 4) << 4));
            LDSM4(ah, qa);
            LDSM4(al, qa + 33792);
            uint32_t ka = sb + 67584u + (uint32_t)((wn * 16 + (lane & 15)) * 528
                           + ds * 32 + ((lane >> 4) << 4));
            LDSM4(kh4, ka);
            LDSM4(kl4, ka + 16896);
            uint32_t bh0[2] = {kh4[0], kh4[2]}, bh1[2] = {kh4[1], kh4[3]};
            uint32_t bl0[2] = {kl4[0], kl4[2]}, bl1[2] = {kl4[1], kl4[3]};
            MMA_BF16(s[0], ah, bh0); MMA_BF16(s[0], ah, bl0); MMA_BF16(s[0], al, bh0);
            MMA_BF16(s[1], ah, bh1); MMA_BF16(s[1], ah, bl1); MMA_BF16(s[1], al, bh1);
        }

#pragma unroll
        for (int nf = 0; nf < 2; nf++)
#pragma unroll
            for (int e = 0; e < 4; e++) {
                int r = wm * 16 + qr + ((e >> 1) * 8);
                int cI = wn * 16 + nf * 8 + qc + (e & 1);
                float v = softcap50(s[nf][e]);
                if (k0r + cI > q0r + r) v = NEGC;
                SS[r * 36 + cI] = v;
            }
        __syncthreads();

        if (t + 1 < nk) {
            const int k1 = (t + 1) * 32;
#pragma unroll
            for (int i = 0; i < 8; i++) {
                int c = tid + (i << 8);
                int op = c >> 10, cc = c & 1023;
                int row = cc >> 5, ch = cc & 31;
                uint32_t dst = sb + 67584u + (uint32_t)(op * 16896 + row * 528 + ch * 16);
                const char* src = (const char*)((op ? Klo : Khi)
                                  + (size_t)(k1 + row) * KDIM + hkv * DH) + ch * 16;
                CP_ASYNC16(dst, src);
            }
            CP_COMMIT();
        }

        {
            int r = tid >> 2, sub = tid & 3;
            const float* rp = SS + r * 36 + sub * 8;
            float mo = m_s[r];
            float v[8];
#pragma unroll
            for (int j = 0; j < 8; j++) v[j] = rp[j];
            float mx8 = v[0];
#pragma unroll
            for (int j = 1; j < 8; j++) mx8 = fmaxf(mx8, v[j]);
            mx8 = fmaxf(mx8, __shfl_xor_sync(0xFFFFFFFFu, mx8, 1));
            mx8 = fmaxf(mx8, __shfl_xor_sync(0xFFFFFFFFu, mx8, 2));
            float mx = fmaxf(mo, mx8);
            float corr = expf(mo - mx);
            __nv_bfloat16* ph = (__nv_bfloat16*)(dsm + 192512) + r * 40 + sub * 8;
            __nv_bfloat16* pl = (__nv_bfloat16*)(dsm + 197632) + r * 40 + sub * 8;
            float sum = 0.0f;
#pragma unroll
            for (int j = 0; j < 8; j++) {
                float p = expf(v[j] - mx);
                sum += p;
                __nv_bfloat16 hh = __float2bfloat16(p);
                ph[j] = hh;
                pl[j] = __float2bfloat16(p - __bfloat162float(hh));
            }
            sum += __shfl_xor_sync(0xFFFFFFFFu, sum, 1);
            sum += __shfl_xor_sync(0xFFFFFFFFu, sum, 2);
            if (sub == 0) {
                m_s[r] = mx;
                l_s[r] = fmaf(l_s[r], corr, sum);
                c_s[r] = corr;
            }
        }
        __syncthreads();

#pragma unroll
        for (int mf = 0; mf < 4; mf++) {
            float c0 = c_s[mf * 16 + qr];
            float c1 = c_s[mf * 16 + qr + 8];
#pragma unroll
            for (int nf = 0; nf < 4; nf++) {
                o[mf][nf][0] *= c0; o[mf][nf][1] *= c0;
                o[mf][nf][2] *= c1; o[mf][nf][3] *= c1;
            }
        }

        const uint32_t vtb = sb + 101376u + (uint32_t)((t & 1) * 40960);
#pragma unroll
        for (int ks = 0; ks < 2; ks++) {
            uint32_t aph[4][4], apl[4][4], bh[4][2], bl[4][2];
#pragma unroll
            for (int mf = 0; mf < 4; mf++) {
                uint32_t pa = sb + 192512u + (uint32_t)((mf * 16 + (lane & 15)) * 80
                               + ks * 32 + ((lane >> 4) << 4));
                LDSM4(aph[mf], pa);
                LDSM4(apl[mf], pa + 5120);
            }
#pragma unroll
            for (int g = 0; g < 2; g++) {
                uint32_t va = vtb + (uint32_t)((warp * 32 + g * 16 + (lane & 15)) * 80
                               + ks * 32 + ((lane >> 4) << 4));
                uint32_t vh4[4], vl4[4];
                LDSM4(vh4, va);
                LDSM4(vl4, va + 20480);
                bh[2 * g][0]     = vh4[0]; bh[2 * g][1]     = vh4[2];
                bh[2 * g + 1][0] = vh4[1]; bh[2 * g + 1][1] = vh4[3];
                bl[2 * g][0]     = vl4[0]; bl[2 * g][1]     = vl4[2];
                bl[2 * g + 1][0] = vl4[1]; bl[2 * g + 1][1] = vl4[3];
            }
#pragma unroll
            for (int mf = 0; mf < 4; mf++)
#pragma unroll
                for (int nf = 0; nf < 4; nf++) {
                    MMA_BF16(o[mf][nf], aph[mf], bh[nf]);
                    MMA_BF16(o[mf][nf], aph[mf], bl[nf]);
                    MMA_BF16(o[mf][nf], apl[mf], bh[nf]);
                }
        }
        __syncthreads();
    }

#pragma unroll
    for (int mf = 0; mf < 4; mf++) {
        float li0 = l_s[mf * 16 + qr];
        float li1 = l_s[mf * 16 + qr + 8];
        int r0 = q0r + mf * 16 + qr;
#pragma unroll
        for (int nf = 0; nf < 4; nf++) {
            int dcol = warp * 32 + nf * 8 + qc;
            size_t o0 = (size_t)r0 * QDIM + h * DH + dcol;
            size_t o1 = (size_t)(r0 + 8) * QDIM + h * DH + dcol;
            float v00 = __fdiv_rn(o[mf][nf][0], li0);
            float v01 = __fdiv_rn(o[mf][nf][1], li0);
            float v10 = __fdiv_rn(o[mf][nf][2], li1);
            float v11 = __fdiv_rn(o[mf][nf][3], li1);
            __nv_bfloat16 h00 = __float2bfloat16(v00), h01 = __float2bfloat16(v01);
            __nv_bfloat16 h10 = __float2bfloat16(v10), h11 = __float2bfloat16(v11);
            *(__nv_bfloat162*)(Ohi + o0) = __nv_bfloat162(h00, h01);
            *(__nv_bfloat162*)(Ohi + o1) = __nv_bfloat162(h10, h11);
            *(__nv_bfloat162*)(Olo + o0) = __nv_bfloat162(
                __float2bfloat16(v00 - __bfloat162float(h00)),
                __float2bfloat16(v01 - __bfloat162float(h01)));
            *(__nv_bfloat162*)(Olo + o1) = __nv_bfloat162(
                __float2bfloat16(v10 - __bfloat162float(h10)),
                __float2bfloat16(v11 - __bfloat162float(h11)));
        }
    }
}

// ===========================================================================
extern "C" void kernel_launch(void* const* d_in, const int* in_sizes, int n_in,
                              void* d_out, int out_size)
{
    const float* x  = (const float*)d_in[0];
    const float* wq = (const float*)d_in[2];
    const float* wk = (const float*)d_in[3];
    const float* wv = (const float*)d_in[4];
    const float* wo = (const float*)d_in[5];
    float* out = (float*)d_out;

    float* pqkv;
    cudaGetSymbolAddress((void**)&pqkv, g_qkv);
    __nv_bfloat16 *xhi, *xlo, *ahi, *alo, *qshi, *qslo, *kshi, *kslo, *vthi, *vtlo;
    __nv_bfloat16 *wqkvh, *wqkvl, *woh, *wol;
    cudaGetSymbolAddress((void**)&xhi,   g_xhi);
    cudaGetSymbolAddress((void**)&xlo,   g_xlo);
    cudaGetSymbolAddress((void**)&ahi,   g_ahi);
    cudaGetSymbolAddress((void**)&alo,   g_alo);
    cudaGetSymbolAddress((void**)&qshi,  g_qhi);
    cudaGetSymbolAddress((void**)&qslo,  g_qlo);
    cudaGetSymbolAddress((void**)&kshi,  g_khi);
    cudaGetSymbolAddress((void**)&kslo,  g_klo);
    cudaGetSymbolAddress((void**)&vthi,  g_vthi);
    cudaGetSymbolAddress((void**)&vtlo,  g_vtlo);
    cudaGetSymbolAddress((void**)&wqkvh, g_wqkvhi);
    cudaGetSymbolAddress((void**)&wqkvl, g_wqkvlo);
    cudaGetSymbolAddress((void**)&woh,   g_wohi);
    cudaGetSymbolAddress((void**)&wol,   g_wolo);

    dim3 blk(256);
    dim3 tb(32, 8);
    const int GEMM_SMEM  = 122880;
    const int FLASH_SMEM = 203520;
    cudaFuncSetAttribute(gemm_mma, cudaFuncAttributeMaxDynamicSharedMemorySize, GEMM_SMEM);
    cudaFuncSetAttribute(flash_mma, cudaFuncAttributeMaxDynamicSharedMemorySize, FLASH_SMEM);

    // index 3 = fused QKV gemm (ncu capture slot)
    {
        int n4 = LSEQ * HID / 4;
        split_kernel<<<(n4 + 255) / 256, blk>>>(x, xhi, xlo, n4);              // 0
    }
    splitT_qkv_kernel<<<dim3(QKVN / 32, HID / 32), tb>>>(wq, wk, wv);          // 1
    splitT_kernel<<<dim3(HID / 32, QDIM / 32), tb>>>(wo, woh, wol, QDIM, HID); // 2
    gemm_mma<<<dim3(QKVN / 256, WIN / 128), blk, GEMM_SMEM>>>(                 // 3
        xhi + (size_t)WIN * HID, xlo + (size_t)WIN * HID, wqkvh, wqkvl,
        pqkv, WIN, QKVN, HID);

    // RoPE + operand prep for flash
    invf_init_kernel<<<1, 128>>>();
    rope_split_kernel<<<WIN, 128>>>(0, NHQ, qshi, qslo);
    rope_split_kernel<<<WIN, 128>>>(QDIM, NKV, kshi, kslo);
    vt_split_kernel<<<dim3(WIN / 32, DH / 32, NKV), tb>>>();

    // lowq rows: xsum -> vmean -> lowrow -> fill
    xsum_part_kernel<<<dim3(9, 16), blk>>>(x);
    xsum_comb_kernel<<<9, blk>>>();
    vmean_part_kernel<<<dim3(4, 8), blk>>>(wv);
    vmean_comb_kernel<<<4, blk>>>();
    lowout_part_kernel<<<dim3(9, 8), blk>>>(wo);
    lowout_comb_kernel<<<9, blk>>>();
    lowfill_kernel<<<(WIN * HID + 255) / 256, blk>>>(out);

    // Flash attention (q >= 2048)
    flash_mma<<<dim3(32, NHQ), blk, FLASH_SMEM>>>(
        qshi, qslo, kshi, kslo, vthi, vtlo, ahi, alo);

    // Output projection: high rows only
    gemm_mma<<<dim3(HID / 256, WIN / 128), blk, GEMM_SMEM>>>(
        ahi, alo, woh, wol, out + (size_t)WIN * HID, WIN, HID, QDIM);
}

// round 13
// speedup vs baseline: 1.0025x; 1.0025x over previous
#include <cuda_runtime.h>
#include <cuda_bf16.h>
#include <math.h>
#include <stdint.h>

#define LSEQ 4096
#define NHQ 8
#define NKV 4
#define DH 256
#define HID 2304
#define WIN 2048
#define QDIM (NHQ*DH)   /* 2048 */
#define KDIM (NKV*DH)   /* 1024 */
#define QKVN (QDIM + 2*KDIM)  /* 4096 fused N */

#define SCALEF 0.05892556509887896f   /* 288^-0.5 */
#define NEGC  (-1.0e9f)

// fused QKV projection output (rows = l - WIN, cols = [q|k|v])
static __device__ float g_qkv[(size_t)WIN * QKVN];
static __device__ float g_vmean[KDIM];
static __device__ float g_lowrow[HID];
static __device__ float g_invf[128];
static __device__ float g_xpart[16 * HID];
static __device__ float g_xsum[HID];
static __device__ float g_vpart[8 * KDIM];
static __device__ float g_lowpart[8 * HID];

// bf16-split operands
static __device__ __nv_bfloat16 g_xhi[(size_t)LSEQ * HID];
static __device__ __nv_bfloat16 g_xlo[(size_t)LSEQ * HID];
static __device__ __nv_bfloat16 g_ahi[(size_t)WIN * QDIM];
static __device__ __nv_bfloat16 g_alo[(size_t)WIN * QDIM];
// roped, compacted (rows = l - WIN)
static __device__ __nv_bfloat16 g_qhi[(size_t)WIN * QDIM];
static __device__ __nv_bfloat16 g_qlo[(size_t)WIN * QDIM];
static __device__ __nv_bfloat16 g_khi[(size_t)WIN * KDIM];
static __device__ __nv_bfloat16 g_klo[(size_t)WIN * KDIM];
// V transposed per kv head: [hkv][d=256][k-WIN=2048]
static __device__ __nv_bfloat16 g_vthi[(size_t)NKV * DH * WIN];
static __device__ __nv_bfloat16 g_vtlo[(size_t)NKV * DH * WIN];
// weights transposed to [N][K] K-major; qkv fused [4096][2304]
static __device__ __nv_bfloat16 g_wqkvhi[(size_t)QKVN * HID];
static __device__ __nv_bfloat16 g_wqkvlo[(size_t)QKVN * HID];
static __device__ __nv_bfloat16 g_wohi[(size_t)HID * QDIM];
static __device__ __nv_bfloat16 g_wolo[(size_t)HID * QDIM];

// ===========================================================================
// Helpers (base-target PTX only)
// ===========================================================================
__device__ __forceinline__ uint32_t smem_u32(const void* p) {
    uint32_t r;
    asm("{ .reg .u64 t; cvta.to.shared.u64 t, %1; cvt.u32.u64 %0, t; }"
        : "=r"(r) : "l"(p));
    return r;
}

#define CP_ASYNC16(dst, src) \
    asm volatile("cp.async.cg.shared.global [%0], [%1], 16;" \
                 :: "r"(dst), "l"(src) : "memory")
#define CP_COMMIT()  asm volatile("cp.async.commit_group;" ::: "memory")
#define CP_WAIT0()   asm volatile("cp.async.wait_group 0;" ::: "memory")
#define CP_WAIT1()   asm volatile("cp.async.wait_group 1;" ::: "memory")

#define LDSM4(R, addr) \
    asm volatile("ldmatrix.sync.aligned.m8n8.x4.shared.b16 {%0,%1,%2,%3}, [%4];" \
        : "=r"((R)[0]), "=r"((R)[1]), "=r"((R)[2]), "=r"((R)[3]) : "r"(addr))

#define MMA_BF16(ACC, A, B) \
    asm volatile("mma.sync.aligned.m16n8k16.row.col.f32.bf16.bf16.f32 " \
        "{%0,%1,%2,%3}, {%4,%5,%6,%7}, {%8,%9}, {%0,%1,%2,%3};" \
        : "+f"((ACC)[0]), "+f"((ACC)[1]), "+f"((ACC)[2]), "+f"((ACC)[3]) \
        : "r"((A)[0]), "r"((A)[1]), "r"((A)[2]), "r"((A)[3]), \
          "r"((B)[0]), "r"((B)[1]))

// ===========================================================================
// bf16-split MMA GEMM, CTA 128x128, BK=32 (R11 shell) with MMA issue
// reordered TERM-OUTERMOST: consecutive MMAs target different accumulators
// (dependency distance 16 instead of 1) to break the acc RAW serialization
// that pinned tensor pipe at ~46%.
// ===========================================================================
__global__ __launch_bounds__(256) void gemm_mma(
    const __nv_bfloat16* __restrict__ Ahi, const __nv_bfloat16* __restrict__ Alo,
    const __nv_bfloat16* __restrict__ Bhi, const __nv_bfloat16* __restrict__ Blo,
    float* __restrict__ C, int M, int N, int K)
{
    extern __shared__ char smdyn[];
    const uint32_t sbase = smem_u32(smdyn);
    const int tid  = threadIdx.x;
    const int warp = tid >> 5;
    const int lane = tid & 31;
    const int wm = warp >> 2;
    const int wn = warp & 3;
    const int row0 = blockIdx.y * 128;
    const int col0 = blockIdx.x * 128;

    const __nv_bfloat16* gsrc[4] = {
        Ahi + (size_t)row0 * K, Alo + (size_t)row0 * K,
        Bhi + (size_t)col0 * K, Blo + (size_t)col0 * K };

    float acc[4][4][4];
#pragma unroll
    for (int a = 0; a < 4; a++)
#pragma unroll
        for (int b = 0; b < 4; b++)
#pragma unroll
            for (int c = 0; c < 4; c++) acc[a][b][c] = 0.0f;

    const int S = K >> 5;

    {
#pragma unroll
        for (int i = 0; i < 8; i++) {
            int c = tid + (i << 8);
            int op = c >> 9, cc = c & 511;
            int row = cc >> 2, kc = cc & 3;
            uint32_t dst = sbase + (uint32_t)(op * 10240 + row * 80 + kc * 16);
            const char* src = (const char*)(gsrc[op] + (size_t)row * K) + kc * 16;
            CP_ASYNC16(dst, src);
        }
        CP_COMMIT();
        CP_WAIT0();
        __syncthreads();
    }

    for (int s = 0; s < S; s++) {
        const int st = s & 1;
        if (s + 1 < S) {
            const int k0 = (s + 1) << 5;
            const uint32_t stoff = (uint32_t)((st ^ 1) * 40960);
#pragma unroll
            for (int i = 0; i < 8; i++) {
                int c = tid + (i << 8);
                int op = c >> 9, cc = c & 511;
                int row = cc >> 2, kc = cc & 3;
                uint32_t dst = sbase + stoff + (uint32_t)(op * 10240 + row * 80 + kc * 16);
                const char* src = (const char*)(gsrc[op] + (size_t)row * K + k0) + kc * 16;
                CP_ASYNC16(dst, src);
            }
            CP_COMMIT();
        }

        const uint32_t base = sbase + (uint32_t)(st * 40960);
#pragma unroll
        for (int t = 0; t < 2; t++) {
            uint32_t ahi[4][4], alo[4][4], bhi[4][2], blo[4][2];
#pragma unroll
            for (int mf = 0; mf < 4; mf++) {
                int r = wm * 64 + mf * 16 + (lane & 15);
                uint32_t ad = base + (uint32_t)(r * 80 + t * 32 + ((lane >> 4) << 4));
                LDSM4(ahi[mf], ad);
                LDSM4(alo[mf], ad + 10240);
            }
#pragma unroll
            for (int g = 0; g < 2; g++) {
                int n = wn * 32 + g * 16 + (lane & 15);
                uint32_t bd = base + 20480u + (uint32_t)(n * 80 + t * 32 + ((lane >> 4) << 4));
                uint32_t h4[4], l4[4];
                LDSM4(h4, bd);
                LDSM4(l4, bd + 10240);
                bhi[2 * g][0]     = h4[0]; bhi[2 * g][1]     = h4[2];
                bhi[2 * g + 1][0] = h4[1]; bhi[2 * g + 1][1] = h4[3];
                blo[2 * g][0]     = l4[0]; blo[2 * g][1]     = l4[2];
                blo[2 * g + 1][0] = l4[1]; blo[2 * g + 1][1] = l4[3];
            }
            // term-outermost: distance-16 accumulator reuse
#pragma unroll
            for (int mf = 0; mf < 4; mf++)
#pragma unroll
                for (int nf = 0; nf < 4; nf++)
                    MMA_BF16(acc[mf][nf], ahi[mf], bhi[nf]);
#pragma unroll
            for (int mf = 0; mf < 4; mf++)
#pragma unroll
                for (int nf = 0; nf < 4; nf++)
                    MMA_BF16(acc[mf][nf], ahi[mf], blo[nf]);
#pragma unroll
            for (int mf = 0; mf < 4; mf++)
#pragma unroll
                for (int nf = 0; nf < 4; nf++)
                    MMA_BF16(acc[mf][nf], alo[mf], bhi[nf]);
        }
        CP_WAIT0();
        __syncthreads();
    }

    const int qr = lane >> 2;
    const int qc = (lane & 3) * 2;
#pragma unroll
    for (int mf = 0; mf < 4; mf++)
#pragma unroll
        for (int nf = 0; nf < 4; nf++) {
            int r = row0 + wm * 64 + mf * 16 + qr;
            int cI = col0 + wn * 32 + nf * 8 + qc;
            float2 v0 = make_float2(acc[mf][nf][0], acc[mf][nf][1]);
            float2 v1 = make_float2(acc[mf][nf][2], acc[mf][nf][3]);
            *(float2*)(C + (size_t)r * N + cI)       = v0;
            *(float2*)(C + (size_t)(r + 8) * N + cI) = v1;
        }
}

// ===========================================================================
// bf16 split conversions
// ===========================================================================
__global__ void split_kernel(const float* __restrict__ src,
                             __nv_bfloat16* __restrict__ hi,
                             __nv_bfloat16* __restrict__ lo, int n4)
{
    int i = blockIdx.x * blockDim.x + threadIdx.x;
    if (i >= n4) return;
    float4 v = *(const float4*)(src + (size_t)i * 4);
    float f[4] = {v.x, v.y, v.z, v.w};
    __nv_bfloat16 h[4], l[4];
#pragma unroll
    for (int j = 0; j < 4; j++) {
        h[j] = __float2bfloat16(f[j]);
        l[j] = __float2bfloat16(f[j] - __bfloat162float(h[j]));
    }
    *(__nv_bfloat162*)(hi + (size_t)i * 4)     = __nv_bfloat162(h[0], h[1]);
    *(__nv_bfloat162*)(hi + (size_t)i * 4 + 2) = __nv_bfloat162(h[2], h[3]);
    *(__nv_bfloat162*)(lo + (size_t)i * 4)     = __nv_bfloat162(l[0], l[1]);
    *(__nv_bfloat162*)(lo + (size_t)i * 4 + 2) = __nv_bfloat162(l[2], l[3]);
}

// Fused transposing split of wq|wk|wv into g_wqkv [4096][2304]
__global__ void splitT_qkv_kernel(const float* __restrict__ wq,
                                  const float* __restrict__ wk,
                                  const float* __restrict__ wv)
{
    __shared__ float t[32][33];
    const int n0 = blockIdx.x * 32;
    const int k0 = blockIdx.y * 32;
    const int tx = threadIdx.x, ty = threadIdx.y;

    const float* W;
    int Nsrc, nb;
    if (n0 < QDIM)             { W = wq; Nsrc = QDIM; nb = n0; }
    else if (n0 < QDIM + KDIM) { W = wk; Nsrc = KDIM; nb = n0 - QDIM; }
    else                       { W = wv; Nsrc = KDIM; nb = n0 - QDIM - KDIM; }

#pragma unroll
    for (int j = 0; j < 4; j++)
        t[ty + j * 8][tx] = W[(size_t)(k0 + ty + j * 8) * Nsrc + nb + tx];
    __syncthreads();
#pragma unroll
    for (int j = 0; j < 4; j++) {
        float v = t[tx][ty + j * 8];
        __nv_bfloat16 h = __float2bfloat16(v);
        __nv_bfloat16 l = __float2bfloat16(v - __bfloat162float(h));
        size_t o = (size_t)(n0 + ty + j * 8) * HID + k0 + tx;
        g_wqkvhi[o] = h;
        g_wqkvlo[o] = l;
    }
}

__global__ void splitT_kernel(const float* __restrict__ W,
                              __nv_bfloat16* __restrict__ hi,
                              __nv_bfloat16* __restrict__ lo, int K, int N)
{
    __shared__ float t[32][33];
    const int n0 = blockIdx.x * 32;
    const int k0 = blockIdx.y * 32;
    const int tx = threadIdx.x, ty = threadIdx.y;
#pragma unroll
    for (int j = 0; j < 4; j++)
        t[ty + j * 8][tx] = W[(size_t)(k0 + ty + j * 8) * N + n0 + tx];
    __syncthreads();
#pragma unroll
    for (int j = 0; j < 4; j++) {
        float v = t[tx][ty + j * 8];
        __nv_bfloat16 h = __float2bfloat16(v);
        __nv_bfloat16 l = __float2bfloat16(v - __bfloat162float(h));
        size_t o = (size_t)(n0 + ty + j * 8) * K + k0 + tx;
        hi[o] = h;
        lo[o] = l;
    }
}

// ===========================================================================
// RoPE: invf table once, trig inline (double range-reduction + __sincosf)
// ===========================================================================
__global__ void invf_init_kernel()
{
    int i = threadIdx.x;
    double ex = (double)(2 * i) / 256.0;
    float pf = (float)pow(10000.0, ex);
    g_invf[i] = __fdiv_rn(1.0f, pf);
}

__global__ void rope_split_kernel(int coloff, int nheads,
                                  __nv_bfloat16* __restrict__ hi,
                                  __nv_bfloat16* __restrict__ lo)
{
    int row = blockIdx.x;
    int l = WIN + row;
    int i = threadIdx.x;
    float ang = (float)l * g_invf[i];
    double a  = (double)ang;
    double kq = rint(a * 0.15915494309189535);
    double r  = fma(-kq, 6.283185307179586, a);
    float s, c;
    __sincosf((float)r, &s, &c);
    int nd = nheads * DH;
    for (int h = 0; h < nheads; h++) {
        size_t base = (size_t)row * QKVN + coloff + (size_t)h * DH;
        float x1 = g_qkv[base + i];
        float x2 = g_qkv[base + i + 128];
        float y1 = x1 * c - x2 * s;
        float y2 = x2 * c + x1 * s;
        size_t o = (size_t)row * nd + (size_t)h * DH;
        __nv_bfloat16 h1 = __float2bfloat16(y1);
        __nv_bfloat16 h2 = __float2bfloat16(y2);
        hi[o + i]       = h1;
        hi[o + i + 128] = h2;
        lo[o + i]       = __float2bfloat16(y1 - __bfloat162float(h1));
        lo[o + i + 128] = __float2bfloat16(y2 - __bfloat162float(h2));
    }
}

// V transpose-split from g_qkv cols [3072..4096) -> Vt[hkv][d][k] bf16 hi/lo
__global__ void vt_split_kernel()
{
    __shared__ float t[32][33];
    const int k0  = blockIdx.x * 32;
    const int d0  = blockIdx.y * 32;
    const int hkv = blockIdx.z;
    const int tx = threadIdx.x, ty = threadIdx.y;
#pragma unroll
    for (int j = 0; j < 4; j++)
        t[ty + j * 8][tx] = g_qkv[(size_t)(k0 + ty + j * 8) * QKVN
                                  + QDIM + KDIM + hkv * DH + d0 + tx];
    __syncthreads();
#pragma unroll
    for (int j = 0; j < 4; j++) {
        float v = t[tx][ty + j * 8];
        __nv_bfloat16 h = __float2bfloat16(v);
        __nv_bfloat16 l = __float2bfloat16(v - __bfloat162float(h));
        size_t o = (size_t)hkv * DH * WIN + (size_t)(d0 + ty + j * 8) * WIN + k0 + tx;
        g_vthi[o] = h;
        g_vtlo[o] = l;
    }
}

// ===========================================================================
// lowq path via linearity: vmean = (sum_l x_l) @ wv / 4096
// ===========================================================================
__global__ void xsum_part_kernel(const float* __restrict__ x)
{
    int j = blockIdx.x * 256 + threadIdx.x;
    if (j >= HID) return;
    int p = blockIdx.y;
    float s = 0.0f;
    for (int l = p * 256; l < (p + 1) * 256; l++)
        s += x[(size_t)l * HID + j];
    g_xpart[p * HID + j] = s;
}
__global__ void xsum_comb_kernel()
{
    int j = blockIdx.x * 256 + threadIdx.x;
    if (j >= HID) return;
    float s = 0.0f;
#pragma unroll
    for (int p = 0; p < 16; p++) s += g_xpart[p * HID + j];
    g_xsum[j] = s;
}
__global__ void vmean_part_kernel(const float* __restrict__ wv)
{
    int d = blockIdx.x * 256 + threadIdx.x;
    if (d >= KDIM) return;
    int p = blockIdx.y;
    float s = 0.0f;
    for (int i = p * 288; i < (p + 1) * 288; i++)
        s = fmaf(g_xsum[i], wv[(size_t)i * KDIM + d], s);
    g_vpart[p * KDIM + d] = s;
}
__global__ void vmean_comb_kernel()
{
    int d = blockIdx.x * 256 + threadIdx.x;
    if (d >= KDIM) return;
    float s = 0.0f;
#pragma unroll
    for (int p = 0; p < 8; p++) s += g_vpart[p * KDIM + d];
    g_vmean[d] = s * (1.0f / 4096.0f);
}
__global__ void lowout_part_kernel(const float* __restrict__ wo)
{
    int j = blockIdx.x * 256 + threadIdx.x;
    if (j >= HID) return;
    int p = blockIdx.y;
    float s = 0.0f;
    for (int i = p * 256; i < (p + 1) * 256; i++) {
        int h = i >> 8, d = i & 255;
        float r = g_vmean[(h >> 1) * 256 + d];
        s = fmaf(r, wo[(size_t)i * HID + j], s);
    }
    g_lowpart[p * HID + j] = s;
}
__global__ void lowout_comb_kernel()
{
    int j = blockIdx.x * 256 + threadIdx.x;
    if (j >= HID) return;
    float s = 0.0f;
#pragma unroll
    for (int p = 0; p < 8; p++) s += g_lowpart[p * HID + j];
    g_lowrow[j] = s;
}
__global__ void lowfill_kernel(float* __restrict__ out)
{
    int idx = blockIdx.x * blockDim.x + threadIdx.x;
    if (idx >= WIN * HID) return;
    out[idx] = g_lowrow[idx % HID];
}

// ===========================================================================
// Fast accurate softcap: tanh via MUFU-backed __expf (~2^-22 rel err)
// ===========================================================================
__device__ __forceinline__ float softcap50(float s)
{
    float x = __fdiv_rn(s * SCALEF, 50.0f);
    x = fminf(fmaxf(x, -15.0f), 15.0f);
    float e = __expf(2.0f * x);
    return 50.0f * __fdiv_rn(e - 1.0f, e + 1.0f);
}

// ===========================================================================
// Tensor-core flash attention (q >= 2048), pipelined; MMA issue reordered
// term-outermost (same RAW-chain fix as the GEMM).
// ===========================================================================
__global__ __launch_bounds__(256) void flash_mma(
    const __nv_bfloat16* __restrict__ Qhi, const __nv_bfloat16* __restrict__ Qlo,
    const __nv_bfloat16* __restrict__ Khi, const __nv_bfloat16* __restrict__ Klo,
    const __nv_bfloat16* __restrict__ Vthi, const __nv_bfloat16* __restrict__ Vtlo,
    __nv_bfloat16* __restrict__ Ohi, __nv_bfloat16* __restrict__ Olo)
{
    extern __shared__ char dsm[];
    const uint32_t sb = smem_u32(dsm);
    float* SS  = (float*)(dsm + 183296);
    float* m_s = (float*)(dsm + 202752);
    float* l_s = (float*)(dsm + 203008);
    float* c_s = (float*)(dsm + 203264);

    const int tid  = threadIdx.x;
    const int warp = tid >> 5;
    const int lane = tid & 31;
    const int h    = blockIdx.y;
    const int hkv  = h >> 1;
    const int it   = 31 - (int)blockIdx.x;
    const int q0r  = it * 64;
    const int nk   = 2 * it + 2;

    const size_t vtbase_g = (size_t)hkv * DH * WIN;

#pragma unroll
    for (int i = 0; i < 16; i++) {
        int c = tid + (i << 8);
        int op = c >> 11, cc = c & 2047;
        int row = cc >> 5, ch = cc & 31;
        uint32_t dst = sb + (uint32_t)(op * 33792 + row * 528 + ch * 16);
        const char* src = (const char*)((op ? Qlo : Qhi)
                          + (size_t)(q0r + row) * QDIM + h * DH) + ch * 16;
        CP_ASYNC16(dst, src);
    }
#pragma unroll
    for (int i = 0; i < 8; i++) {
        int c = tid + (i << 8);
        int op = c >> 10, cc = c & 1023;
        int row = cc >> 5, ch = cc & 31;
        uint32_t dst = sb + 67584u + (uint32_t)(op * 16896 + row * 528 + ch * 16);
        const char* src = (const char*)((op ? Klo : Khi)
                          + (size_t)row * KDIM + hkv * DH) + ch * 16;
        CP_ASYNC16(dst, src);
    }
#pragma unroll
    for (int i = 0; i < 8; i++) {
        int c = tid + (i << 8);
        int op = c >> 10, cc = c & 1023;
        int row = cc >> 2, ch = cc & 3;
        uint32_t dst = sb + 101376u + (uint32_t)(op * 20480 + row * 80 + ch * 16);
        const char* src = (const char*)((op ? Vtlo : Vthi)
                          + vtbase_g + (size_t)row * WIN) + ch * 16;
        CP_ASYNC16(dst, src);
    }
    CP_COMMIT();

    if (tid < 64) { m_s[tid] = -INFINITY; l_s[tid] = 0.0f; }

    float o[4][4][4];
#pragma unroll
    for (int a = 0; a < 4; a++)
#pragma unroll
        for (int b = 0; b < 4; b++)
#pragma unroll
            for (int c = 0; c < 4; c++) o[a][b][c] = 0.0f;

    const int wm = warp >> 1;
    const int wn = warp & 1;
    const int qr = lane >> 2, qc = (lane & 3) * 2;

    for (int t = 0; t < nk; t++) {
        if (t + 1 < nk) {
            const int k1 = (t + 1) * 32;
            const uint32_t vtoff = 101376u + (uint32_t)(((t + 1) & 1) * 40960);
#pragma unroll
            for (int i = 0; i < 8; i++) {
                int c = tid + (i << 8);
                int op = c >> 10, cc = c & 1023;
                int row = cc >> 2, ch = cc & 3;
                uint32_t dst = sb + vtoff + (uint32_t)(op * 20480 + row * 80 + ch * 16);
                const char* src = (const char*)((op ? Vtlo : Vthi)
                                  + vtbase_g + (size_t)row * WIN + k1) + ch * 16;
                CP_ASYNC16(dst, src);
            }
            CP_COMMIT();
            CP_WAIT1();
        } else {
            CP_WAIT0();
        }
        __syncthreads();

        const int k0r = t * 32;

        float s[2][4];
#pragma unroll
        for (int nf = 0; nf < 2; nf++)
#pragma unroll
            for (int e = 0; e < 4; e++) s[nf][e] = 0.0f;

#pragma unroll
        for (int ds = 0; ds < 16; ds++) {
            uint32_t ah[4], al[4], kh4[4], kl4[4];
            uint32_t qa = sb + (uint32_t)((wm * 16 + (lane & 15)) * 528
                           + ds * 32 + ((lane >> 4) << 4));
            LDSM4(ah, qa);
            LDSM4(al, qa + 33792);
            uint32_t ka = sb + 67584u + (uint32_t)((wn * 16 + (lane & 15)) * 528
                           + ds * 32 + ((lane >> 4) << 4));
            LDSM4(kh4, ka);
            LDSM4(kl4, ka + 16896);
            uint32_t bh0[2] = {kh4[0], kh4[2]}, bh1[2] = {kh4[1], kh4[3]};
            uint32_t bl0[2] = {kl4[0], kl4[2]}, bl1[2] = {kl4[1], kl4[3]};
            // term-outermost (distance-2 acc reuse)
            MMA_BF16(s[0], ah, bh0); MMA_BF16(s[1], ah, bh1);
            MMA_BF16(s[0], ah, bl0); MMA_BF16(s[1], ah, bl1);
            MMA_BF16(s[0], al, bh0); MMA_BF16(s[1], al, bh1);
        }

#pragma unroll
        for (int nf = 0; nf < 2; nf++)
#pragma unroll
            for (int e = 0; e < 4; e++) {
                int r = wm * 16 + qr + ((e >> 1) * 8);
                int cI = wn * 16 + nf * 8 + qc + (e & 1);
                float v = softcap50(s[nf][e]);
                if (k0r + cI > q0r + r) v = NEGC;
                SS[r * 36 + cI] = v;
            }
        __syncthreads();

        if (t + 1 < nk) {
            const int k1 = (t + 1) * 32;
#pragma unroll
            for (int i = 0; i < 8; i++) {
                int c = tid + (i << 8);
                int op = c >> 10, cc = c & 1023;
                int row = cc >> 5, ch = cc & 31;
                uint32_t dst = sb + 67584u + (uint32_t)(op * 16896 + row * 528 + ch * 16);
                const char* src = (const char*)((op ? Klo : Khi)
                                  + (size_t)(k1 + row) * KDIM + hkv * DH) + ch * 16;
                CP_ASYNC16(dst, src);
            }
            CP_COMMIT();
        }

        {
            int r = tid >> 2, sub = tid & 3;
            const float* rp = SS + r * 36 + sub * 8;
            float mo = m_s[r];
            float v[8];
#pragma unroll
            for (int j = 0; j < 8; j++) v[j] = rp[j];
            float mx8 = v[0];
#pragma unroll
            for (int j = 1; j < 8; j++) mx8 = fmaxf(mx8, v[j]);
            mx8 = fmaxf(mx8, __shfl_xor_sync(0xFFFFFFFFu, mx8, 1));
            mx8 = fmaxf(mx8, __shfl_xor_sync(0xFFFFFFFFu, mx8, 2));
            float mx = fmaxf(mo, mx8);
            float corr = expf(mo - mx);
            __nv_bfloat16* ph = (__nv_bfloat16*)(dsm + 192512) + r * 40 + sub * 8;
            __nv_bfloat16* pl = (__nv_bfloat16*)(dsm + 197632) + r * 40 + sub * 8;
            float sum = 0.0f;
#pragma unroll
            for (int j = 0; j < 8; j++) {
                float p = expf(v[j] - mx);
                sum += p;
                __nv_bfloat16 hh = __float2bfloat16(p);
                ph[j] = hh;
                pl[j] = __float2bfloat16(p - __bfloat162float(hh));
            }
            sum += __shfl_xor_sync(0xFFFFFFFFu, sum, 1);
            sum += __shfl_xor_sync(0xFFFFFFFFu, sum, 2);
            if (sub == 0) {
                m_s[r] = mx;
                l_s[r] = fmaf(l_s[r], corr, sum);
                c_s[r] = corr;
            }
        }
        __syncthreads();

#pragma unroll
        for (int mf = 0; mf < 4; mf++) {
            float c0 = c_s[mf * 16 + qr];
            float c1 = c_s[mf * 16 + qr + 8];
#pragma unroll
            for (int nf = 0; nf < 4; nf++) {
                o[mf][nf][0] *= c0; o[mf][nf][1] *= c0;
                o[mf][nf][2] *= c1; o[mf][nf][3] *= c1;
            }
        }

        const uint32_t vtb = sb + 101376u + (uint32_t)((t & 1) * 40960);
#pragma unroll
        for (int ks = 0; ks < 2; ks++) {
            uint32_t aph[4][4], apl[4][4], bh[4][2], bl[4][2];
#pragma unroll
            for (int mf = 0; mf < 4; mf++) {
                uint32_t pa = sb + 192512u + (uint32_t)((mf * 16 + (lane & 15)) * 80
                               + ks * 32 + ((lane >> 4) << 4));
                LDSM4(aph[mf], pa);
                LDSM4(apl[mf], pa + 5120);
            }
#pragma unroll
            for (int g = 0; g < 2; g++) {
                uint32_t va = vtb + (uint32_t)((warp * 32 + g * 16 + (lane & 15)) * 80
                               + ks * 32 + ((lane >> 4) << 4));
                uint32_t vh4[4], vl4[4];
                LDSM4(vh4, va);
                LDSM4(vl4, va + 20480);
                bh[2 * g][0]     = vh4[0]; bh[2 * g][1]     = vh4[2];
                bh[2 * g + 1][0] = vh4[1]; bh[2 * g + 1][1] = vh4[3];
                bl[2 * g][0]     = vl4[0]; bl[2 * g][1]     = vl4[2];
                bl[2 * g + 1][0] = vl4[1]; bl[2 * g + 1][1] = vl4[3];
            }
            // term-outermost (distance-16 acc reuse)
#pragma unroll
            for (int mf = 0; mf < 4; mf++)
#pragma unroll
                for (int nf = 0; nf < 4; nf++)
                    MMA_BF16(o[mf][nf], aph[mf], bh[nf]);
#pragma unroll
            for (int mf = 0; mf < 4; mf++)
#pragma unroll
                for (int nf = 0; nf < 4; nf++)
                    MMA_BF16(o[mf][nf], aph[mf], bl[nf]);
#pragma unroll
            for (int mf = 0; mf < 4; mf++)
#pragma unroll
                for (int nf = 0; nf < 4; nf++)
                    MMA_BF16(o[mf][nf], apl[mf], bh[nf]);
        }
        __syncthreads();
    }

#pragma unroll
    for (int mf = 0; mf < 4; mf++) {
        float li0 = l_s[mf * 16 + qr];
        float li1 = l_s[mf * 16 + qr + 8];
        int r0 = q0r + mf * 16 + qr;
#pragma unroll
        for (int nf = 0; nf < 4; nf++) {
            int dcol = warp * 32 + nf * 8 + qc;
            size_t o0 = (size_t)r0 * QDIM + h * DH + dcol;
            size_t o1 = (size_t)(r0 + 8) * QDIM + h * DH + dcol;
            float v00 = __fdiv_rn(o[mf][nf][0], li0);
            float v01 = __fdiv_rn(o[mf][nf][1], li0);
            float v10 = __fdiv_rn(o[mf][nf][2], li1);
            float v11 = __fdiv_rn(o[mf][nf][3], li1);
            __nv_bfloat16 h00 = __float2bfloat16(v00), h01 = __float2bfloat16(v01);
            __nv_bfloat16 h10 = __float2bfloat16(v10), h11 = __float2bfloat16(v11);
            *(__nv_bfloat162*)(Ohi + o0) = __nv_bfloat162(h00, h01);
            *(__nv_bfloat162*)(Ohi + o1) = __nv_bfloat162(h10, h11);
            *(__nv_bfloat162*)(Olo + o0) = __nv_bfloat162(
                __float2bfloat16(v00 - __bfloat162float(h00)),
                __float2bfloat16(v01 - __bfloat162float(h01)));
            *(__nv_bfloat162*)(Olo + o1) = __nv_bfloat162(
                __float2bfloat16(v10 - __bfloat162float(h10)),
                __float2bfloat16(v11 - __bfloat162float(h11)));
        }
    }
}

// ===========================================================================
extern "C" void kernel_launch(void* const* d_in, const int* in_sizes, int n_in,
                              void* d_out, int out_size)
{
    const float* x  = (const float*)d_in[0];
    const float* wq = (const float*)d_in[2];
    const float* wk = (const float*)d_in[3];
    const float* wv = (const float*)d_in[4];
    const float* wo = (const float*)d_in[5];
    float* out = (float*)d_out;

    float* pqkv;
    cudaGetSymbolAddress((void**)&pqkv, g_qkv);
    __nv_bfloat16 *xhi, *xlo, *ahi, *alo, *qshi, *qslo, *kshi, *kslo, *vthi, *vtlo;
    __nv_bfloat16 *wqkvh, *wqkvl, *woh, *wol;
    cudaGetSymbolAddress((void**)&xhi,   g_xhi);
    cudaGetSymbolAddress((void**)&xlo,   g_xlo);
    cudaGetSymbolAddress((void**)&ahi,   g_ahi);
    cudaGetSymbolAddress((void**)&alo,   g_alo);
    cudaGetSymbolAddress((void**)&qshi,  g_qhi);
    cudaGetSymbolAddress((void**)&qslo,  g_qlo);
    cudaGetSymbolAddress((void**)&kshi,  g_khi);
    cudaGetSymbolAddress((void**)&kslo,  g_klo);
    cudaGetSymbolAddress((void**)&vthi,  g_vthi);
    cudaGetSymbolAddress((void**)&vtlo,  g_vtlo);
    cudaGetSymbolAddress((void**)&wqkvh, g_wqkvhi);
    cudaGetSymbolAddress((void**)&wqkvl, g_wqkvlo);
    cudaGetSymbolAddress((void**)&woh,   g_wohi);
    cudaGetSymbolAddress((void**)&wol,   g_wolo);

    dim3 blk(256);
    dim3 tb(32, 8);
    const int GEMM_SMEM  = 81920;
    const int FLASH_SMEM = 203520;
    cudaFuncSetAttribute(gemm_mma, cudaFuncAttributeMaxDynamicSharedMemorySize, GEMM_SMEM);
    cudaFuncSetAttribute(flash_mma, cudaFuncAttributeMaxDynamicSharedMemorySize, FLASH_SMEM);

    // index 3 = fused QKV gemm (ncu capture slot)
    {
        int n4 = LSEQ * HID / 4;
        split_kernel<<<(n4 + 255) / 256, blk>>>(x, xhi, xlo, n4);              // 0
    }
    splitT_qkv_kernel<<<dim3(QKVN / 32, HID / 32), tb>>>(wq, wk, wv);          // 1
    splitT_kernel<<<dim3(HID / 32, QDIM / 32), tb>>>(wo, woh, wol, QDIM, HID); // 2
    gemm_mma<<<dim3(QKVN / 128, WIN / 128), blk, GEMM_SMEM>>>(                 // 3
        xhi + (size_t)WIN * HID, xlo + (size_t)WIN * HID, wqkvh, wqkvl,
        pqkv, WIN, QKVN, HID);

    // RoPE + operand prep for flash
    invf_init_kernel<<<1, 128>>>();
    rope_split_kernel<<<WIN, 128>>>(0, NHQ, qshi, qslo);
    rope_split_kernel<<<WIN, 128>>>(QDIM, NKV, kshi, kslo);
    vt_split_kernel<<<dim3(WIN / 32, DH / 32, NKV), tb>>>();

    // lowq rows: xsum -> vmean -> lowrow -> fill
    xsum_part_kernel<<<dim3(9, 16), blk>>>(x);
    xsum_comb_kernel<<<9, blk>>>();
    vmean_part_kernel<<<dim3(4, 8), blk>>>(wv);
    vmean_comb_kernel<<<4, blk>>>();
    lowout_part_kernel<<<dim3(9, 8), blk>>>(wo);
    lowout_comb_kernel<<<9, blk>>>();
    lowfill_kernel<<<(WIN * HID + 255) / 256, blk>>>(out);

    // Flash attention (q >= 2048)
    flash_mma<<<dim3(32, NHQ), blk, FLASH_SMEM>>>(
        qshi, qslo, kshi, kslo, vthi, vtlo, ahi, alo);

    // Output projection: high rows only
    gemm_mma<<<dim3(HID / 128, WIN / 128), blk, GEMM_SMEM>>>(
        ahi, alo, woh, wol, out + (size_t)WIN * HID, WIN, HID, QDIM);
}

// round 14
// speedup vs baseline: 1.1992x; 1.1962x over previous
#include <cuda_runtime.h>
#include <cuda_fp16.h>
#include <math.h>
#include <stdint.h>

#define LSEQ 4096
#define NHQ 8
#define NKV 4
#define DH 256
#define HID 2304
#define WIN 2048
#define QDIM (NHQ*DH)   /* 2048 */
#define KDIM (NKV*DH)   /* 1024 */
#define QKVN (QDIM + 2*KDIM)  /* 4096 fused N */

#define SCALEF 0.05892556509887896f   /* 288^-0.5 */
#define NEGC  (-1.0e9f)

// fused QKV projection output (rows = l - WIN, cols = [q|k|v])
static __device__ float g_qkv[(size_t)WIN * QKVN];
static __device__ float g_vmean[KDIM];
static __device__ float g_lowrow[HID];
static __device__ float g_invf[128];
static __device__ float g_xpart[16 * HID];
static __device__ float g_xsum[HID];
static __device__ float g_vpart[8 * KDIM];
static __device__ float g_lowpart[8 * HID];

// fp16-split operands
static __device__ __half g_xhi[(size_t)LSEQ * HID];
static __device__ __half g_xlo[(size_t)LSEQ * HID];
static __device__ __half g_ahi[(size_t)WIN * QDIM];
static __device__ __half g_alo[(size_t)WIN * QDIM];
// roped, compacted (rows = l - WIN)
static __device__ __half g_qhi[(size_t)WIN * QDIM];
static __device__ __half g_qlo[(size_t)WIN * QDIM];
static __device__ __half g_khi[(size_t)WIN * KDIM];
static __device__ __half g_klo[(size_t)WIN * KDIM];
// V transposed per kv head: [hkv][d=256][k-WIN=2048]
static __device__ __half g_vthi[(size_t)NKV * DH * WIN];
static __device__ __half g_vtlo[(size_t)NKV * DH * WIN];
// weights single-rounded fp16, transposed to [N][K] K-major
static __device__ __half g_wqkv16[(size_t)QKVN * HID];
static __device__ __half g_wo16[(size_t)HID * QDIM];

// ===========================================================================
// Helpers (base-target PTX only)
// ===========================================================================
__device__ __forceinline__ uint32_t smem_u32(const void* p) {
    uint32_t r;
    asm("{ .reg .u64 t; cvta.to.shared.u64 t, %1; cvt.u32.u64 %0, t; }"
        : "=r"(r) : "l"(p));
    return r;
}

#define CP_ASYNC16(dst, src) \
    asm volatile("cp.async.cg.shared.global [%0], [%1], 16;" \
                 :: "r"(dst), "l"(src) : "memory")
#define CP_COMMIT()  asm volatile("cp.async.commit_group;" ::: "memory")
#define CP_WAIT0()   asm volatile("cp.async.wait_group 0;" ::: "memory")
#define CP_WAIT1()   asm volatile("cp.async.wait_group 1;" ::: "memory")

#define LDSM4(R, addr) \
    asm volatile("ldmatrix.sync.aligned.m8n8.x4.shared.b16 {%0,%1,%2,%3}, [%4];" \
        : "=r"((R)[0]), "=r"((R)[1]), "=r"((R)[2]), "=r"((R)[3]) : "r"(addr))

#define MMA16(ACC, A, B) \
    asm volatile("mma.sync.aligned.m16n8k16.row.col.f32.f16.f16.f32 " \
        "{%0,%1,%2,%3}, {%4,%5,%6,%7}, {%8,%9}, {%0,%1,%2,%3};" \
        : "+f"((ACC)[0]), "+f"((ACC)[1]), "+f"((ACC)[2]), "+f"((ACC)[3]) \
        : "r"((A)[0]), "r"((A)[1]), "r"((A)[2]), "r"((A)[3]), \
          "r"((B)[0]), "r"((B)[1]))

__device__ __forceinline__ void split2h(float f, __half& h, __half& l)
{
    h = __float2half_rn(f);
    l = __float2half_rn(f - __half2float(h));
}

// ===========================================================================
// fp16 2-term MMA GEMM: C[M,N] = (Ahi+Alo)[M,K] @ B16[N,K]^T (fp32 out).
// CTA 128x128, BK=32, double-buffered. 32 MMAs / 12 LDSM per k16-step pair.
// Stage layout: Ahi@0, Alo@10240, B@20480 (each 128 rows x 80 B);
// stage stride 30720, 2 stages = 61440 B dynamic smem.
// ===========================================================================
__global__ __launch_bounds__(256) void gemm_mma(
    const __half* __restrict__ Ahi, const __half* __restrict__ Alo,
    const __half* __restrict__ B,
    float* __restrict__ C, int M, int N, int K)
{
    extern __shared__ char smdyn[];
    const uint32_t sbase = smem_u32(smdyn);
    const int tid  = threadIdx.x;
    const int warp = tid >> 5;
    const int lane = tid & 31;
    const int wm = warp >> 2;
    const int wn = warp & 3;
    const int row0 = blockIdx.y * 128;
    const int col0 = blockIdx.x * 128;

    const __half* gsrc[3] = {
        Ahi + (size_t)row0 * K, Alo + (size_t)row0 * K, B + (size_t)col0 * K };

    float acc[4][4][4];
#pragma unroll
    for (int a = 0; a < 4; a++)
#pragma unroll
        for (int b = 0; b < 4; b++)
#pragma unroll
            for (int c = 0; c < 4; c++) acc[a][b][c] = 0.0f;

    const int S = K >> 5;

#define GEMM_COPY_SLAB(stoff, k0)                                            \
    do {                                                                     \
        _Pragma("unroll")                                                    \
        for (int i = 0; i < 6; i++) {                                       \
            int c = tid + (i << 8);                                          \
            int op = c >> 9, cc = c & 511;                                   \
            int row = cc >> 2, kc = cc & 3;                                  \
            uint32_t dst = sbase + (uint32_t)(stoff) +                       \
                           (uint32_t)(op * 10240 + row * 80 + kc * 16);      \
            const char* src = (const char*)(gsrc[op] + (size_t)row * K + (k0)) + kc * 16; \
            CP_ASYNC16(dst, src);                                            \
        }                                                                    \
    } while (0)

    GEMM_COPY_SLAB(0, 0);
    CP_COMMIT();
    CP_WAIT0();
    __syncthreads();

    for (int s = 0; s < S; s++) {
        const int st = s & 1;
        if (s + 1 < S) {
            GEMM_COPY_SLAB((st ^ 1) * 30720, (s + 1) << 5);
            CP_COMMIT();
        }

        const uint32_t base = sbase + (uint32_t)(st * 30720);
#pragma unroll
        for (int t = 0; t < 2; t++) {
            uint32_t ah[4][4], al[4][4], bf[4][2];
#pragma unroll
            for (int mf = 0; mf < 4; mf++) {
                int r = wm * 64 + mf * 16 + (lane & 15);
                uint32_t ad = base + (uint32_t)(r * 80 + t * 32 + ((lane >> 4) << 4));
                LDSM4(ah[mf], ad);
                LDSM4(al[mf], ad + 10240);
            }
#pragma unroll
            for (int g = 0; g < 2; g++) {
                int n = wn * 32 + g * 16 + (lane & 15);
                uint32_t bd = base + 20480u + (uint32_t)(n * 80 + t * 32 + ((lane >> 4) << 4));
                uint32_t h4[4];
                LDSM4(h4, bd);
                bf[2 * g][0]     = h4[0]; bf[2 * g][1]     = h4[2];
                bf[2 * g + 1][0] = h4[1]; bf[2 * g + 1][1] = h4[3];
            }
#pragma unroll
            for (int mf = 0; mf < 4; mf++)
#pragma unroll
                for (int nf = 0; nf < 4; nf++)
                    MMA16(acc[mf][nf], ah[mf], bf[nf]);
#pragma unroll
            for (int mf = 0; mf < 4; mf++)
#pragma unroll
                for (int nf = 0; nf < 4; nf++)
                    MMA16(acc[mf][nf], al[mf], bf[nf]);
        }
        CP_WAIT0();
        __syncthreads();
    }

    const int qr = lane >> 2;
    const int qc = (lane & 3) * 2;
#pragma unroll
    for (int mf = 0; mf < 4; mf++)
#pragma unroll
        for (int nf = 0; nf < 4; nf++) {
            int r = row0 + wm * 64 + mf * 16 + qr;
            int cI = col0 + wn * 32 + nf * 8 + qc;
            float2 v0 = make_float2(acc[mf][nf][0], acc[mf][nf][1]);
            float2 v1 = make_float2(acc[mf][nf][2], acc[mf][nf][3]);
            *(float2*)(C + (size_t)r * N + cI)       = v0;
            *(float2*)(C + (size_t)(r + 8) * N + cI) = v1;
        }
}

// ===========================================================================
// fp16 split conversions
// ===========================================================================
__global__ void split_kernel(const float* __restrict__ src,
                             __half* __restrict__ hi,
                             __half* __restrict__ lo, int n4)
{
    int i = blockIdx.x * blockDim.x + threadIdx.x;
    if (i >= n4) return;
    float4 v = *(const float4*)(src + (size_t)i * 4);
    float f[4] = {v.x, v.y, v.z, v.w};
    __half h[4], l[4];
#pragma unroll
    for (int j = 0; j < 4; j++) split2h(f[j], h[j], l[j]);
    *(__half2*)(hi + (size_t)i * 4)     = __halves2half2(h[0], h[1]);
    *(__half2*)(hi + (size_t)i * 4 + 2) = __halves2half2(h[2], h[3]);
    *(__half2*)(lo + (size_t)i * 4)     = __halves2half2(l[0], l[1]);
    *(__half2*)(lo + (size_t)i * 4 + 2) = __halves2half2(l[2], l[3]);
}

// Fused transposing single-round of wq|wk|wv into g_wqkv16 [4096][2304]
__global__ void splitT_qkv_kernel(const float* __restrict__ wq,
                                  const float* __restrict__ wk,
                                  const float* __restrict__ wv)
{
    __shared__ float t[32][33];
    const int n0 = blockIdx.x * 32;
    const int k0 = blockIdx.y * 32;
    const int tx = threadIdx.x, ty = threadIdx.y;

    const float* W;
    int Nsrc, nb;
    if (n0 < QDIM)             { W = wq; Nsrc = QDIM; nb = n0; }
    else if (n0 < QDIM + KDIM) { W = wk; Nsrc = KDIM; nb = n0 - QDIM; }
    else                       { W = wv; Nsrc = KDIM; nb = n0 - QDIM - KDIM; }

#pragma unroll
    for (int j = 0; j < 4; j++)
        t[ty + j * 8][tx] = W[(size_t)(k0 + ty + j * 8) * Nsrc + nb + tx];
    __syncthreads();
#pragma unroll
    for (int j = 0; j < 4; j++) {
        float v = t[tx][ty + j * 8];
        g_wqkv16[(size_t)(n0 + ty + j * 8) * HID + k0 + tx] = __float2half_rn(v);
    }
}

__global__ void splitT_wo_kernel(const float* __restrict__ W)
{
    __shared__ float t[32][33];
    const int n0 = blockIdx.x * 32;    // HID cols
    const int k0 = blockIdx.y * 32;    // QDIM rows
    const int tx = threadIdx.x, ty = threadIdx.y;
#pragma unroll
    for (int j = 0; j < 4; j++)
        t[ty + j * 8][tx] = W[(size_t)(k0 + ty + j * 8) * HID + n0 + tx];
    __syncthreads();
#pragma unroll
    for (int j = 0; j < 4; j++) {
        float v = t[tx][ty + j * 8];
        g_wo16[(size_t)(n0 + ty + j * 8) * QDIM + k0 + tx] = __float2half_rn(v);
    }
}

// ===========================================================================
// RoPE: invf table once, trig inline (double range-reduction + __sincosf)
// ===========================================================================
__global__ void invf_init_kernel()
{
    int i = threadIdx.x;
    double ex = (double)(2 * i) / 256.0;
    float pf = (float)pow(10000.0, ex);
    g_invf[i] = __fdiv_rn(1.0f, pf);
}

__global__ void rope_split_kernel(int coloff, int nheads,
                                  __half* __restrict__ hi,
                                  __half* __restrict__ lo)
{
    int row = blockIdx.x;
    int l = WIN + row;
    int i = threadIdx.x;
    float ang = (float)l * g_invf[i];
    double a  = (double)ang;
    double kq = rint(a * 0.15915494309189535);
    double r  = fma(-kq, 6.283185307179586, a);
    float s, c;
    __sincosf((float)r, &s, &c);
    int nd = nheads * DH;
    for (int h = 0; h < nheads; h++) {
        size_t base = (size_t)row * QKVN + coloff + (size_t)h * DH;
        float x1 = g_qkv[base + i];
        float x2 = g_qkv[base + i + 128];
        float y1 = x1 * c - x2 * s;
        float y2 = x2 * c + x1 * s;
        size_t o = (size_t)row * nd + (size_t)h * DH;
        __half h1, l1, h2, l2;
        split2h(y1, h1, l1);
        split2h(y2, h2, l2);
        hi[o + i]       = h1;
        hi[o + i + 128] = h2;
        lo[o + i]       = l1;
        lo[o + i + 128] = l2;
    }
}

// V transpose-split from g_qkv cols [3072..4096) -> Vt[hkv][d][k] fp16 hi/lo
__global__ void vt_split_kernel()
{
    __shared__ float t[32][33];
    const int k0  = blockIdx.x * 32;
    const int d0  = blockIdx.y * 32;
    const int hkv = blockIdx.z;
    const int tx = threadIdx.x, ty = threadIdx.y;
#pragma unroll
    for (int j = 0; j < 4; j++)
        t[ty + j * 8][tx] = g_qkv[(size_t)(k0 + ty + j * 8) * QKVN
                                  + QDIM + KDIM + hkv * DH + d0 + tx];
    __syncthreads();
#pragma unroll
    for (int j = 0; j < 4; j++) {
        float v = t[tx][ty + j * 8];
        __half h, l;
        split2h(v, h, l);
        size_t o = (size_t)hkv * DH * WIN + (size_t)(d0 + ty + j * 8) * WIN + k0 + tx;
        g_vthi[o] = h;
        g_vtlo[o] = l;
    }
}

// ===========================================================================
// lowq path via linearity: vmean = (sum_l x_l) @ wv / 4096
// ===========================================================================
__global__ void xsum_part_kernel(const float* __restrict__ x)
{
    int j = blockIdx.x * 256 + threadIdx.x;
    if (j >= HID) return;
    int p = blockIdx.y;
    float s = 0.0f;
    for (int l = p * 256; l < (p + 1) * 256; l++)
        s += x[(size_t)l * HID + j];
    g_xpart[p * HID + j] = s;
}
__global__ void xsum_comb_kernel()
{
    int j = blockIdx.x * 256 + threadIdx.x;
    if (j >= HID) return;
    float s = 0.0f;
#pragma unroll
    for (int p = 0; p < 16; p++) s += g_xpart[p * HID + j];
    g_xsum[j] = s;
}
__global__ void vmean_part_kernel(const float* __restrict__ wv)
{
    int d = blockIdx.x * 256 + threadIdx.x;
    if (d >= KDIM) return;
    int p = blockIdx.y;
    float s = 0.0f;
    for (int i = p * 288; i < (p + 1) * 288; i++)
        s = fmaf(g_xsum[i], wv[(size_t)i * KDIM + d], s);
    g_vpart[p * KDIM + d] = s;
}
__global__ void vmean_comb_kernel()
{
    int d = blockIdx.x * 256 + threadIdx.x;
    if (d >= KDIM) return;
    float s = 0.0f;
#pragma unroll
    for (int p = 0; p < 8; p++) s += g_vpart[p * KDIM + d];
    g_vmean[d] = s * (1.0f / 4096.0f);
}
__global__ void lowout_part_kernel(const float* __restrict__ wo)
{
    int j = blockIdx.x * 256 + threadIdx.x;
    if (j >= HID) return;
    int p = blockIdx.y;
    float s = 0.0f;
    for (int i = p * 256; i < (p + 1) * 256; i++) {
        int h = i >> 8, d = i & 255;
        float r = g_vmean[(h >> 1) * 256 + d];
        s = fmaf(r, wo[(size_t)i * HID + j], s);
    }
    g_lowpart[p * HID + j] = s;
}
__global__ void lowout_comb_kernel()
{
    int j = blockIdx.x * 256 + threadIdx.x;
    if (j >= HID) return;
    float s = 0.0f;
#pragma unroll
    for (int p = 0; p < 8; p++) s += g_lowpart[p * HID + j];
    g_lowrow[j] = s;
}
__global__ void lowfill_kernel(float* __restrict__ out)
{
    int idx = blockIdx.x * blockDim.x + threadIdx.x;
    if (idx >= WIN * HID) return;
    out[idx] = g_lowrow[idx % HID];
}

// ===========================================================================
// Fast accurate softcap: tanh via MUFU-backed __expf (~2^-22 rel err)
// ===========================================================================
__device__ __forceinline__ float softcap50(float s)
{
    float x = __fdiv_rn(s * SCALEF, 50.0f);
    x = fminf(fmaxf(x, -15.0f), 15.0f);
    float e = __expf(2.0f * x);
    return 50.0f * __fdiv_rn(e - 1.0f, e + 1.0f);
}

// ===========================================================================
// Tensor-core flash attention (q >= 2048), pipelined; fp16 3-term split
// (same shell as R10-R13, dtype swapped bf16->fp16).
// ===========================================================================
__global__ __launch_bounds__(256) void flash_mma(
    const __half* __restrict__ Qhi, const __half* __restrict__ Qlo,
    const __half* __restrict__ Khi, const __half* __restrict__ Klo,
    const __half* __restrict__ Vthi, const __half* __restrict__ Vtlo,
    __half* __restrict__ Ohi, __half* __restrict__ Olo)
{
    extern __shared__ char dsm[];
    const uint32_t sb = smem_u32(dsm);
    float* SS  = (float*)(dsm + 183296);
    float* m_s = (float*)(dsm + 202752);
    float* l_s = (float*)(dsm + 203008);
    float* c_s = (float*)(dsm + 203264);

    const int tid  = threadIdx.x;
    const int warp = tid >> 5;
    const int lane = tid & 31;
    const int h    = blockIdx.y;
    const int hkv  = h >> 1;
    const int it   = 31 - (int)blockIdx.x;
    const int q0r  = it * 64;
    const int nk   = 2 * it + 2;

    const size_t vtbase_g = (size_t)hkv * DH * WIN;

#pragma unroll
    for (int i = 0; i < 16; i++) {
        int c = tid + (i << 8);
        int op = c >> 11, cc = c & 2047;
        int row = cc >> 5, ch = cc & 31;
        uint32_t dst = sb + (uint32_t)(op * 33792 + row * 528 + ch * 16);
        const char* src = (const char*)((op ? Qlo : Qhi)
                          + (size_t)(q0r + row) * QDIM + h * DH) + ch * 16;
        CP_ASYNC16(dst, src);
    }
#pragma unroll
    for (int i = 0; i < 8; i++) {
        int c = tid + (i << 8);
        int op = c >> 10, cc = c & 1023;
        int row = cc >> 5, ch = cc & 31;
        uint32_t dst = sb + 67584u + (uint32_t)(op * 16896 + row * 528 + ch * 16);
        const char* src = (const char*)((op ? Klo : Khi)
                          + (size_t)row * KDIM + hkv * DH) + ch * 16;
        CP_ASYNC16(dst, src);
    }
#pragma unroll
    for (int i = 0; i < 8; i++) {
        int c = tid + (i << 8);
        int op = c >> 10, cc = c & 1023;
        int row = cc >> 2, ch = cc & 3;
        uint32_t dst = sb + 101376u + (uint32_t)(op * 20480 + row * 80 + ch * 16);
        const char* src = (const char*)((op ? Vtlo : Vthi)
                          + vtbase_g + (size_t)row * WIN) + ch * 16;
        CP_ASYNC16(dst, src);
    }
    CP_COMMIT();

    if (tid < 64) { m_s[tid] = -INFINITY; l_s[tid] = 0.0f; }

    float o[4][4][4];
#pragma unroll
    for (int a = 0; a < 4; a++)
#pragma unroll
        for (int b = 0; b < 4; b++)
#pragma unroll
            for (int c = 0; c < 4; c++) o[a][b][c] = 0.0f;

    const int wm = warp >> 1;
    const int wn = warp & 1;
    const int qr = lane >> 2, qc = (lane & 3) * 2;

    for (int t = 0; t < nk; t++) {
        if (t + 1 < nk) {
            const int k1 = (t + 1) * 32;
            const uint32_t vtoff = 101376u + (uint32_t)(((t + 1) & 1) * 40960);
#pragma unroll
            for (int i = 0; i < 8; i++) {
                int c = tid + (i << 8);
                int op = c >> 10, cc = c & 1023;
                int row = cc >> 2, ch = cc & 3;
                uint32_t dst = sb + vtoff + (uint32_t)(op * 20480 + row * 80 + ch * 16);
                const char* src = (const char*)((op ? Vtlo : Vthi)
                                  + vtbase_g + (size_t)row * WIN + k1) + ch * 16;
                CP_ASYNC16(dst, src);
            }
            CP_COMMIT();
            CP_WAIT1();
        } else {
            CP_WAIT0();
        }
        __syncthreads();

        const int k0r = t * 32;

        float s[2][4];
#pragma unroll
        for (int nf = 0; nf < 2; nf++)
#pragma unroll
            for (int e = 0; e < 4; e++) s[nf][e] = 0.0f;

#pragma unroll
        for (int ds = 0; ds < 16; ds++) {
            uint32_t ah[4], al[4], kh4[4], kl4[4];
            uint32_t qa = sb + (uint32_t)((wm * 16 + (lane & 15)) * 528
                           + ds * 32 + ((lane >> 4) << 4));
            LDSM4(ah, qa);
            LDSM4(al, qa + 33792);
            uint32_t ka = sb + 67584u + (uint32_t)((wn * 16 + (lane & 15)) * 528
                           + ds * 32 + ((lane >> 4) << 4));
            LDSM4(kh4, ka);
            LDSM4(kl4, ka + 16896);
            uint32_t bh0[2] = {kh4[0], kh4[2]}, bh1[2] = {kh4[1], kh4[3]};
            uint32_t bl0[2] = {kl4[0], kl4[2]}, bl1[2] = {kl4[1], kl4[3]};
            MMA16(s[0], ah, bh0); MMA16(s[1], ah, bh1);
            MMA16(s[0], ah, bl0); MMA16(s[1], ah, bl1);
            MMA16(s[0], al, bh0); MMA16(s[1], al, bh1);
        }

#pragma unroll
        for (int nf = 0; nf < 2; nf++)
#pragma unroll
            for (int e = 0; e < 4; e++) {
                int r = wm * 16 + qr + ((e >> 1) * 8);
                int cI = wn * 16 + nf * 8 + qc + (e & 1);
                float v = softcap50(s[nf][e]);
                if (k0r + cI > q0r + r) v = NEGC;
                SS[r * 36 + cI] = v;
            }
        __syncthreads();

        if (t + 1 < nk) {
            const int k1 = (t + 1) * 32;
#pragma unroll
            for (int i = 0; i < 8; i++) {
                int c = tid + (i << 8);
                int op = c >> 10, cc = c & 1023;
                int row = cc >> 5, ch = cc & 31;
                uint32_t dst = sb + 67584u + (uint32_t)(op * 16896 + row * 528 + ch * 16);
                const char* src = (const char*)((op ? Klo : Khi)
                                  + (size_t)(k1 + row) * KDIM + hkv * DH) + ch * 16;
                CP_ASYNC16(dst, src);
            }
            CP_COMMIT();
        }

        {
            int r = tid >> 2, sub = tid & 3;
            const float* rp = SS + r * 36 + sub * 8;
            float mo = m_s[r];
            float v[8];
#pragma unroll
            for (int j = 0; j < 8; j++) v[j] = rp[j];
            float mx8 = v[0];
#pragma unroll
            for (int j = 1; j < 8; j++) mx8 = fmaxf(mx8, v[j]);
            mx8 = fmaxf(mx8, __shfl_xor_sync(0xFFFFFFFFu, mx8, 1));
            mx8 = fmaxf(mx8, __shfl_xor_sync(0xFFFFFFFFu, mx8, 2));
            float mx = fmaxf(mo, mx8);
            float corr = expf(mo - mx);
            __half* ph = (__half*)(dsm + 192512) + r * 40 + sub * 8;
            __half* pl = (__half*)(dsm + 197632) + r * 40 + sub * 8;
            float sum = 0.0f;
#pragma unroll
            for (int j = 0; j < 8; j++) {
                float p = expf(v[j] - mx);
                sum += p;
                __half hh, hl;
                split2h(p, hh, hl);
                ph[j] = hh;
                pl[j] = hl;
            }
            sum += __shfl_xor_sync(0xFFFFFFFFu, sum, 1);
            sum += __shfl_xor_sync(0xFFFFFFFFu, sum, 2);
            if (sub == 0) {
                m_s[r] = mx;
                l_s[r] = fmaf(l_s[r], corr, sum);
                c_s[r] = corr;
            }
        }
        __syncthreads();

#pragma unroll
        for (int mf = 0; mf < 4; mf++) {
            float c0 = c_s[mf * 16 + qr];
            float c1 = c_s[mf * 16 + qr + 8];
#pragma unroll
            for (int nf = 0; nf < 4; nf++) {
                o[mf][nf][0] *= c0; o[mf][nf][1] *= c0;
                o[mf][nf][2] *= c1; o[mf][nf][3] *= c1;
            }
        }

        const uint32_t vtb = sb + 101376u + (uint32_t)((t & 1) * 40960);
#pragma unroll
        for (int ks = 0; ks < 2; ks++) {
            uint32_t aph[4][4], apl[4][4], bh[4][2], bl[4][2];
#pragma unroll
            for (int mf = 0; mf < 4; mf++) {
                uint32_t pa = sb + 192512u + (uint32_t)((mf * 16 + (lane & 15)) * 80
                               + ks * 32 + ((lane >> 4) << 4));
                LDSM4(aph[mf], pa);
                LDSM4(apl[mf], pa + 5120);
            }
#pragma unroll
            for (int g = 0; g < 2; g++) {
                uint32_t va = vtb + (uint32_t)((warp * 32 + g * 16 + (lane & 15)) * 80
                               + ks * 32 + ((lane >> 4) << 4));
                uint32_t vh4[4], vl4[4];
                LDSM4(vh4, va);
                LDSM4(vl4, va + 20480);
                bh[2 * g][0]     = vh4[0]; bh[2 * g][1]     = vh4[2];
                bh[2 * g + 1][0] = vh4[1]; bh[2 * g + 1][1] = vh4[3];
                bl[2 * g][0]     = vl4[0]; bl[2 * g][1]     = vl4[2];
                bl[2 * g + 1][0] = vl4[1]; bl[2 * g + 1][1] = vl4[3];
            }
#pragma unroll
            for (int mf = 0; mf < 4; mf++)
#pragma unroll
                for (int nf = 0; nf < 4; nf++)
                    MMA16(o[mf][nf], aph[mf], bh[nf]);
#pragma unroll
            for (int mf = 0; mf < 4; mf++)
#pragma unroll
                for (int nf = 0; nf < 4; nf++)
                    MMA16(o[mf][nf], aph[mf], bl[nf]);
#pragma unroll
            for (int mf = 0; mf < 4; mf++)
#pragma unroll
                for (int nf = 0; nf < 4; nf++)
                    MMA16(o[mf][nf], apl[mf], bh[nf]);
        }
        __syncthreads();
    }

#pragma unroll
    for (int mf = 0; mf < 4; mf++) {
        float li0 = l_s[mf * 16 + qr];
        float li1 = l_s[mf * 16 + qr + 8];
        int r0 = q0r + mf * 16 + qr;
#pragma unroll
        for (int nf = 0; nf < 4; nf++) {
            int dcol = warp * 32 + nf * 8 + qc;
            size_t o0 = (size_t)r0 * QDIM + h * DH + dcol;
            size_t o1 = (size_t)(r0 + 8) * QDIM + h * DH + dcol;
            float v00 = __fdiv_rn(o[mf][nf][0], li0);
            float v01 = __fdiv_rn(o[mf][nf][1], li0);
            float v10 = __fdiv_rn(o[mf][nf][2], li1);
            float v11 = __fdiv_rn(o[mf][nf][3], li1);
            __half h00, l00, h01, l01, h10, l10, h11, l11;
            split2h(v00, h00, l00);
            split2h(v01, h01, l01);
            split2h(v10, h10, l10);
            split2h(v11, h11, l11);
            *(__half2*)(Ohi + o0) = __halves2half2(h00, h01);
            *(__half2*)(Ohi + o1) = __halves2half2(h10, h11);
            *(__half2*)(Olo + o0) = __halves2half2(l00, l01);
            *(__half2*)(Olo + o1) = __halves2half2(l10, l11);
        }
    }
}

// ===========================================================================
extern "C" void kernel_launch(void* const* d_in, const int* in_sizes, int n_in,
                              void* d_out, int out_size)
{
    const float* x  = (const float*)d_in[0];
    const float* wq = (const float*)d_in[2];
    const float* wk = (const float*)d_in[3];
    const float* wv = (const float*)d_in[4];
    const float* wo = (const float*)d_in[5];
    float* out = (float*)d_out;

    float* pqkv;
    cudaGetSymbolAddress((void**)&pqkv, g_qkv);
    __half *xhi, *xlo, *ahi, *alo, *qshi, *qslo, *kshi, *kslo, *vthi, *vtlo;
    __half *wqkv16, *wo16;
    cudaGetSymbolAddress((void**)&xhi,    g_xhi);
    cudaGetSymbolAddress((void**)&xlo,    g_xlo);
    cudaGetSymbolAddress((void**)&ahi,    g_ahi);
    cudaGetSymbolAddress((void**)&alo,    g_alo);
    cudaGetSymbolAddress((void**)&qshi,   g_qhi);
    cudaGetSymbolAddress((void**)&qslo,   g_qlo);
    cudaGetSymbolAddress((void**)&kshi,   g_khi);
    cudaGetSymbolAddress((void**)&kslo,   g_klo);
    cudaGetSymbolAddress((void**)&vthi,   g_vthi);
    cudaGetSymbolAddress((void**)&vtlo,   g_vtlo);
    cudaGetSymbolAddress((void**)&wqkv16, g_wqkv16);
    cudaGetSymbolAddress((void**)&wo16,   g_wo16);

    dim3 blk(256);
    dim3 tb(32, 8);
    const int GEMM_SMEM  = 61440;
    const int FLASH_SMEM = 203520;
    cudaFuncSetAttribute(gemm_mma, cudaFuncAttributeMaxDynamicSharedMemorySize, GEMM_SMEM);
    cudaFuncSetAttribute(flash_mma, cudaFuncAttributeMaxDynamicSharedMemorySize, FLASH_SMEM);

    // index 3 = fused QKV gemm (ncu capture slot)
    {
        int n4 = LSEQ * HID / 4;
        split_kernel<<<(n4 + 255) / 256, blk>>>(x, xhi, xlo, n4);              // 0
    }
    splitT_qkv_kernel<<<dim3(QKVN / 32, HID / 32), tb>>>(wq, wk, wv);          // 1
    splitT_wo_kernel<<<dim3(HID / 32, QDIM / 32), tb>>>(wo);                   // 2
    gemm_mma<<<dim3(QKVN / 128, WIN / 128), blk, GEMM_SMEM>>>(                 // 3
        xhi + (size_t)WIN * HID, xlo + (size_t)WIN * HID, wqkv16,
        pqkv, WIN, QKVN, HID);

    // RoPE + operand prep for flash
    invf_init_kernel<<<1, 128>>>();
    rope_split_kernel<<<WIN, 128>>>(0, NHQ, qshi, qslo);
    rope_split_kernel<<<WIN, 128>>>(QDIM, NKV, kshi, kslo);
    vt_split_kernel<<<dim3(WIN / 32, DH / 32, NKV), tb>>>();

    // lowq rows: xsum -> vmean -> lowrow -> fill
    xsum_part_kernel<<<dim3(9, 16), blk>>>(x);
    xsum_comb_kernel<<<9, blk>>>();
    vmean_part_kernel<<<dim3(4, 8), blk>>>(wv);
    vmean_comb_kernel<<<4, blk>>>();
    lowout_part_kernel<<<dim3(9, 8), blk>>>(wo);
    lowout_comb_kernel<<<9, blk>>>();
    lowfill_kernel<<<(WIN * HID + 255) / 256, blk>>>(out);

    // Flash attention (q >= 2048)
    flash_mma<<<dim3(32, NHQ), blk, FLASH_SMEM>>>(
        qshi, qslo, kshi, kslo, vthi, vtlo, ahi, alo);

    // Output projection: high rows only
    gemm_mma<<<dim3(HID / 128, WIN / 128), blk, GEMM_SMEM>>>(
        ahi, alo, wo16, out + (size_t)WIN * HID, WIN, HID, QDIM);
}

// round 15
// speedup vs baseline: 1.3375x; 1.1154x over previous
#include <cuda_runtime.h>
#include <cuda_fp16.h>
#include <math.h>
#include <stdint.h>

#define LSEQ 4096
#define NHQ 8
#define NKV 4
#define DH 256
#define HID 2304
#define WIN 2048
#define QDIM (NHQ*DH)   /* 2048 */
#define KDIM (NKV*DH)   /* 1024 */
#define QKVN (QDIM + 2*KDIM)  /* 4096 fused N */

#define SCALEF 0.05892556509887896f   /* 288^-0.5 */
#define NEGC  (-1.0e9f)

// fused QKV projection output (rows = l - WIN, cols = [q|k|v])
static __device__ float g_qkv[(size_t)WIN * QKVN];
static __device__ float g_vmean[KDIM];
static __device__ float g_lowrow[HID];
static __device__ float g_invf[128];
static __device__ float g_xpart[16 * HID];
static __device__ float g_xsum[HID];
static __device__ float g_vpart[8 * KDIM];
static __device__ float g_lowpart[8 * HID];

// fp16-split operands (x: only rows >= WIN, compacted)
static __device__ __half g_xhi[(size_t)WIN * HID];
static __device__ __half g_xlo[(size_t)WIN * HID];
static __device__ __half g_ahi[(size_t)WIN * QDIM];
static __device__ __half g_alo[(size_t)WIN * QDIM];
// roped, compacted (rows = l - WIN); Q split, K single-rounded
static __device__ __half g_qhi[(size_t)WIN * QDIM];
static __device__ __half g_qlo[(size_t)WIN * QDIM];
static __device__ __half g_k16[(size_t)WIN * KDIM];
// V transposed per kv head, single-rounded: [hkv][d=256][k-WIN=2048]
static __device__ __half g_vt16[(size_t)NKV * DH * WIN];
// weights single-rounded fp16, transposed to [N][K] K-major
static __device__ __half g_wqkv16[(size_t)QKVN * HID];
static __device__ __half g_wo16[(size_t)HID * QDIM];

// ===========================================================================
// Helpers (base-target PTX only)
// ===========================================================================
__device__ __forceinline__ uint32_t smem_u32(const void* p) {
    uint32_t r;
    asm("{ .reg .u64 t; cvta.to.shared.u64 t, %1; cvt.u32.u64 %0, t; }"
        : "=r"(r) : "l"(p));
    return r;
}

#define CP_ASYNC16(dst, src) \
    asm volatile("cp.async.cg.shared.global [%0], [%1], 16;" \
                 :: "r"(dst), "l"(src) : "memory")
#define CP_COMMIT()  asm volatile("cp.async.commit_group;" ::: "memory")
#define CP_WAIT0()   asm volatile("cp.async.wait_group 0;" ::: "memory")
#define CP_WAIT1()   asm volatile("cp.async.wait_group 1;" ::: "memory")

#define LDSM4(R, addr) \
    asm volatile("ldmatrix.sync.aligned.m8n8.x4.shared.b16 {%0,%1,%2,%3}, [%4];" \
        : "=r"((R)[0]), "=r"((R)[1]), "=r"((R)[2]), "=r"((R)[3]) : "r"(addr))

#define MMA16(ACC, A, B) \
    asm volatile("mma.sync.aligned.m16n8k16.row.col.f32.f16.f16.f32 " \
        "{%0,%1,%2,%3}, {%4,%5,%6,%7}, {%8,%9}, {%0,%1,%2,%3};" \
        : "+f"((ACC)[0]), "+f"((ACC)[1]), "+f"((ACC)[2]), "+f"((ACC)[3]) \
        : "r"((A)[0]), "r"((A)[1]), "r"((A)[2]), "r"((A)[3]), \
          "r"((B)[0]), "r"((B)[1]))

__device__ __forceinline__ void split2h(float f, __half& h, __half& l)
{
    h = __float2half_rn(f);
    l = __float2half_rn(f - __half2float(h));
}

// ===========================================================================
// fp16 2-term MMA GEMM (validated R14): C = (Ahi+Alo) @ B16^T, fp32 out.
// CTA 128x128, BK=32, double-buffered. Stage: Ahi@0, Alo@10240, B@20480;
// stride 30720, 2 stages = 61440 B.
// ===========================================================================
__global__ __launch_bounds__(256) void gemm_mma(
    const __half* __restrict__ Ahi, const __half* __restrict__ Alo,
    const __half* __restrict__ B,
    float* __restrict__ C, int M, int N, int K)
{
    extern __shared__ char smdyn[];
    const uint32_t sbase = smem_u32(smdyn);
    const int tid  = threadIdx.x;
    const int warp = tid >> 5;
    const int lane = tid & 31;
    const int wm = warp >> 2;
    const int wn = warp & 3;
    const int row0 = blockIdx.y * 128;
    const int col0 = blockIdx.x * 128;

    const __half* gsrc[3] = {
        Ahi + (size_t)row0 * K, Alo + (size_t)row0 * K, B + (size_t)col0 * K };

    float acc[4][4][4];
#pragma unroll
    for (int a = 0; a < 4; a++)
#pragma unroll
        for (int b = 0; b < 4; b++)
#pragma unroll
            for (int c = 0; c < 4; c++) acc[a][b][c] = 0.0f;

    const int S = K >> 5;

#define GEMM_COPY_SLAB(stoff, k0)                                            \
    do {                                                                     \
        _Pragma("unroll")                                                    \
        for (int i = 0; i < 6; i++) {                                       \
            int c = tid + (i << 8);                                          \
            int op = c >> 9, cc = c & 511;                                   \
            int row = cc >> 2, kc = cc & 3;                                  \
            uint32_t dst = sbase + (uint32_t)(stoff) +                       \
                           (uint32_t)(op * 10240 + row * 80 + kc * 16);      \
            const char* src = (const char*)(gsrc[op] + (size_t)row * K + (k0)) + kc * 16; \
            CP_ASYNC16(dst, src);                                            \
        }                                                                    \
    } while (0)

    GEMM_COPY_SLAB(0, 0);
    CP_COMMIT();
    CP_WAIT0();
    __syncthreads();

    for (int s = 0; s < S; s++) {
        const int st = s & 1;
        if (s + 1 < S) {
            GEMM_COPY_SLAB((st ^ 1) * 30720, (s + 1) << 5);
            CP_COMMIT();
        }

        const uint32_t base = sbase + (uint32_t)(st * 30720);
#pragma unroll
        for (int t = 0; t < 2; t++) {
            uint32_t ah[4][4], al[4][4], bf[4][2];
#pragma unroll
            for (int mf = 0; mf < 4; mf++) {
                int r = wm * 64 + mf * 16 + (lane & 15);
                uint32_t ad = base + (uint32_t)(r * 80 + t * 32 + ((lane >> 4) << 4));
                LDSM4(ah[mf], ad);
                LDSM4(al[mf], ad + 10240);
            }
#pragma unroll
            for (int g = 0; g < 2; g++) {
                int n = wn * 32 + g * 16 + (lane & 15);
                uint32_t bd = base + 20480u + (uint32_t)(n * 80 + t * 32 + ((lane >> 4) << 4));
                uint32_t h4[4];
                LDSM4(h4, bd);
                bf[2 * g][0]     = h4[0]; bf[2 * g][1]     = h4[2];
                bf[2 * g + 1][0] = h4[1]; bf[2 * g + 1][1] = h4[3];
            }
#pragma unroll
            for (int mf = 0; mf < 4; mf++)
#pragma unroll
                for (int nf = 0; nf < 4; nf++)
                    MMA16(acc[mf][nf], ah[mf], bf[nf]);
#pragma unroll
            for (int mf = 0; mf < 4; mf++)
#pragma unroll
                for (int nf = 0; nf < 4; nf++)
                    MMA16(acc[mf][nf], al[mf], bf[nf]);
        }
        CP_WAIT0();
        __syncthreads();
    }

    const int qr = lane >> 2;
    const int qc = (lane & 3) * 2;
#pragma unroll
    for (int mf = 0; mf < 4; mf++)
#pragma unroll
        for (int nf = 0; nf < 4; nf++) {
            int r = row0 + wm * 64 + mf * 16 + qr;
            int cI = col0 + wn * 32 + nf * 8 + qc;
            float2 v0 = make_float2(acc[mf][nf][0], acc[mf][nf][1]);
            float2 v1 = make_float2(acc[mf][nf][2], acc[mf][nf][3]);
            *(float2*)(C + (size_t)r * N + cI)       = v0;
            *(float2*)(C + (size_t)(r + 8) * N + cI) = v1;
        }
}

// ===========================================================================
// fp16 split conversions
// ===========================================================================
__global__ void split_kernel(const float* __restrict__ src,
                             __half* __restrict__ hi,
                             __half* __restrict__ lo, int n4)
{
    int i = blockIdx.x * blockDim.x + threadIdx.x;
    if (i >= n4) return;
    float4 v = *(const float4*)(src + (size_t)i * 4);
    float f[4] = {v.x, v.y, v.z, v.w};
    __half h[4], l[4];
#pragma unroll
    for (int j = 0; j < 4; j++) split2h(f[j], h[j], l[j]);
    *(__half2*)(hi + (size_t)i * 4)     = __halves2half2(h[0], h[1]);
    *(__half2*)(hi + (size_t)i * 4 + 2) = __halves2half2(h[2], h[3]);
    *(__half2*)(lo + (size_t)i * 4)     = __halves2half2(l[0], l[1]);
    *(__half2*)(lo + (size_t)i * 4 + 2) = __halves2half2(l[2], l[3]);
}

// Fused transposing single-round of wq|wk|wv into g_wqkv16 [4096][2304]
__global__ void splitT_qkv_kernel(const float* __restrict__ wq,
                                  const float* __restrict__ wk,
                                  const float* __restrict__ wv)
{
    __shared__ float t[32][33];
    const int n0 = blockIdx.x * 32;
    const int k0 = blockIdx.y * 32;
    const int tx = threadIdx.x, ty = threadIdx.y;

    const float* W;
    int Nsrc, nb;
    if (n0 < QDIM)             { W = wq; Nsrc = QDIM; nb = n0; }
    else if (n0 < QDIM + KDIM) { W = wk; Nsrc = KDIM; nb = n0 - QDIM; }
    else                       { W = wv; Nsrc = KDIM; nb = n0 - QDIM - KDIM; }

#pragma unroll
    for (int j = 0; j < 4; j++)
        t[ty + j * 8][tx] = W[(size_t)(k0 + ty + j * 8) * Nsrc + nb + tx];
    __syncthreads();
#pragma unroll
    for (int j = 0; j < 4; j++) {
        float v = t[tx][ty + j * 8];
        g_wqkv16[(size_t)(n0 + ty + j * 8) * HID + k0 + tx] = __float2half_rn(v);
    }
}

__global__ void splitT_wo_kernel(const float* __restrict__ W)
{
    __shared__ float t[32][33];
    const int n0 = blockIdx.x * 32;
    const int k0 = blockIdx.y * 32;
    const int tx = threadIdx.x, ty = threadIdx.y;
#pragma unroll
    for (int j = 0; j < 4; j++)
        t[ty + j * 8][tx] = W[(size_t)(k0 + ty + j * 8) * HID + n0 + tx];
    __syncthreads();
#pragma unroll
    for (int j = 0; j < 4; j++) {
        float v = t[tx][ty + j * 8];
        g_wo16[(size_t)(n0 + ty + j * 8) * QDIM + k0 + tx] = __float2half_rn(v);
    }
}

// ===========================================================================
// RoPE: invf table once, trig inline
// ===========================================================================
__global__ void invf_init_kernel()
{
    int i = threadIdx.x;
    double ex = (double)(2 * i) / 256.0;
    float pf = (float)pow(10000.0, ex);
    g_invf[i] = __fdiv_rn(1.0f, pf);
}

// RoPE + fp16 conversion; lo == nullptr -> single-rounded only
__global__ void rope_split_kernel(int coloff, int nheads,
                                  __half* __restrict__ hi,
                                  __half* __restrict__ lo)
{
    int row = blockIdx.x;
    int l = WIN + row;
    int i = threadIdx.x;
    float ang = (float)l * g_invf[i];
    double a  = (double)ang;
    double kq = rint(a * 0.15915494309189535);
    double r  = fma(-kq, 6.283185307179586, a);
    float s, c;
    __sincosf((float)r, &s, &c);
    int nd = nheads * DH;
    for (int h = 0; h < nheads; h++) {
        size_t base = (size_t)row * QKVN + coloff + (size_t)h * DH;
        float x1 = g_qkv[base + i];
        float x2 = g_qkv[base + i + 128];
        float y1 = x1 * c - x2 * s;
        float y2 = x2 * c + x1 * s;
        size_t o = (size_t)row * nd + (size_t)h * DH;
        __half h1 = __float2half_rn(y1);
        __half h2 = __float2half_rn(y2);
        hi[o + i]       = h1;
        hi[o + i + 128] = h2;
        if (lo) {
            lo[o + i]       = __float2half_rn(y1 - __half2float(h1));
            lo[o + i + 128] = __float2half_rn(y2 - __half2float(h2));
        }
    }
}

// V transpose, single-rounded fp16: g_qkv cols [3072..4096) -> Vt[hkv][d][k]
__global__ void vt_split_kernel()
{
    __shared__ float t[32][33];
    const int k0  = blockIdx.x * 32;
    const int d0  = blockIdx.y * 32;
    const int hkv = blockIdx.z;
    const int tx = threadIdx.x, ty = threadIdx.y;
#pragma unroll
    for (int j = 0; j < 4; j++)
        t[ty + j * 8][tx] = g_qkv[(size_t)(k0 + ty + j * 8) * QKVN
                                  + QDIM + KDIM + hkv * DH + d0 + tx];
    __syncthreads();
#pragma unroll
    for (int j = 0; j < 4; j++) {
        float v = t[tx][ty + j * 8];
        size_t o = (size_t)hkv * DH * WIN + (size_t)(d0 + ty + j * 8) * WIN + k0 + tx;
        g_vt16[o] = __float2half_rn(v);
    }
}

// ===========================================================================
// lowq path via linearity: vmean = (sum_l x_l) @ wv / 4096
// ===========================================================================
__global__ void xsum_part_kernel(const float* __restrict__ x)
{
    int j = blockIdx.x * 256 + threadIdx.x;
    if (j >= HID) return;
    int p = blockIdx.y;
    float s = 0.0f;
    for (int l = p * 256; l < (p + 1) * 256; l++)
        s += x[(size_t)l * HID + j];
    g_xpart[p * HID + j] = s;
}
__global__ void xsum_comb_kernel()
{
    int j = blockIdx.x * 256 + threadIdx.x;
    if (j >= HID) return;
    float s = 0.0f;
#pragma unroll
    for (int p = 0; p < 16; p++) s += g_xpart[p * HID + j];
    g_xsum[j] = s;
}
__global__ void vmean_part_kernel(const float* __restrict__ wv)
{
    int d = blockIdx.x * 256 + threadIdx.x;
    if (d >= KDIM) return;
    int p = blockIdx.y;
    float s = 0.0f;
    for (int i = p * 288; i < (p + 1) * 288; i++)
        s = fmaf(g_xsum[i], wv[(size_t)i * KDIM + d], s);
    g_vpart[p * KDIM + d] = s;
}
__global__ void vmean_comb_kernel()
{
    int d = blockIdx.x * 256 + threadIdx.x;
    if (d >= KDIM) return;
    float s = 0.0f;
#pragma unroll
    for (int p = 0; p < 8; p++) s += g_vpart[p * KDIM + d];
    g_vmean[d] = s * (1.0f / 4096.0f);
}
__global__ void lowout_part_kernel(const float* __restrict__ wo)
{
    int j = blockIdx.x * 256 + threadIdx.x;
    if (j >= HID) return;
    int p = blockIdx.y;
    float s = 0.0f;
    for (int i = p * 256; i < (p + 1) * 256; i++) {
        int h = i >> 8, d = i & 255;
        float r = g_vmean[(h >> 1) * 256 + d];
        s = fmaf(r, wo[(size_t)i * HID + j], s);
    }
    g_lowpart[p * HID + j] = s;
}
__global__ void lowout_comb_kernel()
{
    int j = blockIdx.x * 256 + threadIdx.x;
    if (j >= HID) return;
    float s = 0.0f;
#pragma unroll
    for (int p = 0; p < 8; p++) s += g_lowpart[p * HID + j];
    g_lowrow[j] = s;
}
__global__ void lowfill_kernel(float* __restrict__ out)
{
    int idx = blockIdx.x * blockDim.x + threadIdx.x;
    if (idx >= WIN * HID) return;
    out[idx] = g_lowrow[idx % HID];
}

// ===========================================================================
// Fast accurate softcap: tanh via MUFU-backed __expf
// ===========================================================================
__device__ __forceinline__ float softcap50(float s)
{
    float x = __fdiv_rn(s * SCALEF, 50.0f);
    x = fminf(fmaxf(x, -15.0f), 15.0f);
    float e = __expf(2.0f * x);
    return 50.0f * __fdiv_rn(e - 1.0f, e + 1.0f);
}

// ===========================================================================
// Tensor-core flash attention (q >= 2048), pipelined.
// QK 2-term (Q split, K single); PV 2-term (P split, V single).
// SMEM map (bytes):
//   QHI 0 (64x528)    QLO 33792             [end 67584]
//   K   67584 (32x528, single)              [end 84480]
//   VT0 84480 (256x80) VT1 104960           [end 125440]
//   SS  125440 (64x36x4=9216)               [end 134656]
//   PHI 134656 (64x80) PLO 139776           [end 144896]
//   m 144896  l 145152  c 145408            [total 145664]
// ===========================================================================
__global__ __launch_bounds__(256) void flash_mma(
    const __half* __restrict__ Qhi, const __half* __restrict__ Qlo,
    const __half* __restrict__ K16,
    const __half* __restrict__ Vt16,
    __half* __restrict__ Ohi, __half* __restrict__ Olo)
{
    extern __shared__ char dsm[];
    const uint32_t sb = smem_u32(dsm);
    float* SS  = (float*)(dsm + 125440);
    float* m_s = (float*)(dsm + 144896);
    float* l_s = (float*)(dsm + 145152);
    float* c_s = (float*)(dsm + 145408);

    const int tid  = threadIdx.x;
    const int warp = tid >> 5;
    const int lane = tid & 31;
    const int h    = blockIdx.y;
    const int hkv  = h >> 1;
    const int it   = 31 - (int)blockIdx.x;
    const int q0r  = it * 64;
    const int nk   = 2 * it + 2;

    const size_t vtbase_g = (size_t)hkv * DH * WIN;

    // prologue: Q (hi+lo), K(0), VT(0)
#pragma unroll
    for (int i = 0; i < 16; i++) {
        int c = tid + (i << 8);
        int op = c >> 11, cc = c & 2047;
        int row = cc >> 5, ch = cc & 31;
        uint32_t dst = sb + (uint32_t)(op * 33792 + row * 528 + ch * 16);
        const char* src = (const char*)((op ? Qlo : Qhi)
                          + (size_t)(q0r + row) * QDIM + h * DH) + ch * 16;
        CP_ASYNC16(dst, src);
    }
#pragma unroll
    for (int i = 0; i < 4; i++) {
        int c = tid + (i << 8);                // 0..1023: 32 rows x 32 chunks
        int row = c >> 5, ch = c & 31;
        uint32_t dst = sb + 67584u + (uint32_t)(row * 528 + ch * 16);
        const char* src = (const char*)(K16 + (size_t)row * KDIM + hkv * DH) + ch * 16;
        CP_ASYNC16(dst, src);
    }
#pragma unroll
    for (int i = 0; i < 4; i++) {
        int c = tid + (i << 8);                // 0..1023: 256 rows x 4 chunks
        int row = c >> 2, ch = c & 3;
        uint32_t dst = sb + 84480u + (uint32_t)(row * 80 + ch * 16);
        const char* src = (const char*)(Vt16 + vtbase_g + (size_t)row * WIN) + ch * 16;
        CP_ASYNC16(dst, src);
    }
    CP_COMMIT();

    if (tid < 64) { m_s[tid] = -INFINITY; l_s[tid] = 0.0f; }

    float o[4][4][4];
#pragma unroll
    for (int a = 0; a < 4; a++)
#pragma unroll
        for (int b = 0; b < 4; b++)
#pragma unroll
            for (int c = 0; c < 4; c++) o[a][b][c] = 0.0f;

    const int wm = warp >> 1;
    const int wn = warp & 1;
    const int qr = lane >> 2, qc = (lane & 3) * 2;

    for (int t = 0; t < nk; t++) {
        // prefetch VT(t+1)
        if (t + 1 < nk) {
            const int k1 = (t + 1) * 32;
            const uint32_t vtoff = 84480u + (uint32_t)(((t + 1) & 1) * 20480);
#pragma unroll
            for (int i = 0; i < 4; i++) {
                int c = tid + (i << 8);
                int row = c >> 2, ch = c & 3;
                uint32_t dst = sb + vtoff + (uint32_t)(row * 80 + ch * 16);
                const char* src = (const char*)(Vt16 + vtbase_g + (size_t)row * WIN + k1) + ch * 16;
                CP_ASYNC16(dst, src);
            }
            CP_COMMIT();
            CP_WAIT1();
        } else {
            CP_WAIT0();
        }
        __syncthreads();

        const int k0r = t * 32;

        // ---- QK^T: 2-term (Qh+Ql)·K ----
        float s[2][4];
#pragma unroll
        for (int nf = 0; nf < 2; nf++)
#pragma unroll
            for (int e = 0; e < 4; e++) s[nf][e] = 0.0f;

#pragma unroll
        for (int ds = 0; ds < 16; ds++) {
            uint32_t ah[4], al[4], kh4[4];
            uint32_t qa = sb + (uint32_t)((wm * 16 + (lane & 15)) * 528
                           + ds * 32 + ((lane >> 4) << 4));
            LDSM4(ah, qa);
            LDSM4(al, qa + 33792);
            uint32_t ka = sb + 67584u + (uint32_t)((wn * 16 + (lane & 15)) * 528
                           + ds * 32 + ((lane >> 4) << 4));
            LDSM4(kh4, ka);
            uint32_t bh0[2] = {kh4[0], kh4[2]}, bh1[2] = {kh4[1], kh4[3]};
            MMA16(s[0], ah, bh0); MMA16(s[1], ah, bh1);
            MMA16(s[0], al, bh0); MMA16(s[1], al, bh1);
        }

#pragma unroll
        for (int nf = 0; nf < 2; nf++)
#pragma unroll
            for (int e = 0; e < 4; e++) {
                int r = wm * 16 + qr + ((e >> 1) * 8);
                int cI = wn * 16 + nf * 8 + qc + (e & 1);
                float v = softcap50(s[nf][e]);
                if (k0r + cI > q0r + r) v = NEGC;
                SS[r * 36 + cI] = v;
            }
        __syncthreads();

        // issue K(t+1)
        if (t + 1 < nk) {
            const int k1 = (t + 1) * 32;
#pragma unroll
            for (int i = 0; i < 4; i++) {
                int c = tid + (i << 8);
                int row = c >> 5, ch = c & 31;
                uint32_t dst = sb + 67584u + (uint32_t)(row * 528 + ch * 16);
                const char* src = (const char*)(K16 + (size_t)(k1 + row) * KDIM + hkv * DH) + ch * 16;
                CP_ASYNC16(dst, src);
            }
            CP_COMMIT();
        }

        // ---- parallel softmax: 4 threads per row ----
        {
            int r = tid >> 2, sub = tid & 3;
            const float* rp = SS + r * 36 + sub * 8;
            float mo = m_s[r];
            float v[8];
#pragma unroll
            for (int j = 0; j < 8; j++) v[j] = rp[j];
            float mx8 = v[0];
#pragma unroll
            for (int j = 1; j < 8; j++) mx8 = fmaxf(mx8, v[j]);
            mx8 = fmaxf(mx8, __shfl_xor_sync(0xFFFFFFFFu, mx8, 1));
            mx8 = fmaxf(mx8, __shfl_xor_sync(0xFFFFFFFFu, mx8, 2));
            float mx = fmaxf(mo, mx8);
            float corr = expf(mo - mx);
            __half* ph = (__half*)(dsm + 134656) + r * 40 + sub * 8;
            __half* pl = (__half*)(dsm + 139776) + r * 40 + sub * 8;
            float sum = 0.0f;
#pragma unroll
            for (int j = 0; j < 8; j++) {
                float p = expf(v[j] - mx);
                sum += p;
                __half hh, hl;
                split2h(p, hh, hl);
                ph[j] = hh;
                pl[j] = hl;
            }
            sum += __shfl_xor_sync(0xFFFFFFFFu, sum, 1);
            sum += __shfl_xor_sync(0xFFFFFFFFu, sum, 2);
            if (sub == 0) {
                m_s[r] = mx;
                l_s[r] = fmaf(l_s[r], corr, sum);
                c_s[r] = corr;
            }
        }
        __syncthreads();

        // ---- rescale O ----
#pragma unroll
        for (int mf = 0; mf < 4; mf++) {
            float c0 = c_s[mf * 16 + qr];
            float c1 = c_s[mf * 16 + qr + 8];
#pragma unroll
            for (int nf = 0; nf < 4; nf++) {
                o[mf][nf][0] *= c0; o[mf][nf][1] *= c0;
                o[mf][nf][2] *= c1; o[mf][nf][3] *= c1;
            }
        }

        // ---- PV: 2-term (Ph+Pl)·V ----
        const uint32_t vtb = sb + 84480u + (uint32_t)((t & 1) * 20480);
#pragma unroll
        for (int ks = 0; ks < 2; ks++) {
            uint32_t aph[4][4], apl[4][4], bh[4][2];
#pragma unroll
            for (int mf = 0; mf < 4; mf++) {
                uint32_t pa = sb + 134656u + (uint32_t)((mf * 16 + (lane & 15)) * 80
                               + ks * 32 + ((lane >> 4) << 4));
                LDSM4(aph[mf], pa);
                LDSM4(apl[mf], pa + 5120);
            }
#pragma unroll
            for (int g = 0; g < 2; g++) {
                uint32_t va = vtb + (uint32_t)((warp * 32 + g * 16 + (lane & 15)) * 80
                               + ks * 32 + ((lane >> 4) << 4));
                uint32_t vh4[4];
                LDSM4(vh4, va);
                bh[2 * g][0]     = vh4[0]; bh[2 * g][1]     = vh4[2];
                bh[2 * g + 1][0] = vh4[1]; bh[2 * g + 1][1] = vh4[3];
            }
#pragma unroll
            for (int mf = 0; mf < 4; mf++)
#pragma unroll
                for (int nf = 0; nf < 4; nf++)
                    MMA16(o[mf][nf], aph[mf], bh[nf]);
#pragma unroll
            for (int mf = 0; mf < 4; mf++)
#pragma unroll
                for (int nf = 0; nf < 4; nf++)
                    MMA16(o[mf][nf], apl[mf], bh[nf]);
        }
        __syncthreads();
    }

    // ---- epilogue ----
#pragma unroll
    for (int mf = 0; mf < 4; mf++) {
        float li0 = l_s[mf * 16 + qr];
        float li1 = l_s[mf * 16 + qr + 8];
        int r0 = q0r + mf * 16 + qr;
#pragma unroll
        for (int nf = 0; nf < 4; nf++) {
            int dcol = warp * 32 + nf * 8 + qc;
            size_t o0 = (size_t)r0 * QDIM + h * DH + dcol;
            size_t o1 = (size_t)(r0 + 8) * QDIM + h * DH + dcol;
            float v00 = __fdiv_rn(o[mf][nf][0], li0);
            float v01 = __fdiv_rn(o[mf][nf][1], li0);
            float v10 = __fdiv_rn(o[mf][nf][2], li1);
            float v11 = __fdiv_rn(o[mf][nf][3], li1);
            __half h00, l00, h01, l01, h10, l10, h11, l11;
            split2h(v00, h00, l00);
            split2h(v01, h01, l01);
            split2h(v10, h10, l10);
            split2h(v11, h11, l11);
            *(__half2*)(Ohi + o0) = __halves2half2(h00, h01);
            *(__half2*)(Ohi + o1) = __halves2half2(h10, h11);
            *(__half2*)(Olo + o0) = __halves2half2(l00, l01);
            *(__half2*)(Olo + o1) = __halves2half2(l10, l11);
        }
    }
}

// ===========================================================================
extern "C" void kernel_launch(void* const* d_in, const int* in_sizes, int n_in,
                              void* d_out, int out_size)
{
    const float* x  = (const float*)d_in[0];
    const float* wq = (const float*)d_in[2];
    const float* wk = (const float*)d_in[3];
    const float* wv = (const float*)d_in[4];
    const float* wo = (const float*)d_in[5];
    float* out = (float*)d_out;

    float* pqkv;
    cudaGetSymbolAddress((void**)&pqkv, g_qkv);
    __half *xhi, *xlo, *ahi, *alo, *qshi, *qslo, *k16, *vt16;
    __half *wqkv16, *wo16;
    cudaGetSymbolAddress((void**)&xhi,    g_xhi);
    cudaGetSymbolAddress((void**)&xlo,    g_xlo);
    cudaGetSymbolAddress((void**)&ahi,    g_ahi);
    cudaGetSymbolAddress((void**)&alo,    g_alo);
    cudaGetSymbolAddress((void**)&qshi,   g_qhi);
    cudaGetSymbolAddress((void**)&qslo,   g_qlo);
    cudaGetSymbolAddress((void**)&k16,    g_k16);
    cudaGetSymbolAddress((void**)&vt16,   g_vt16);
    cudaGetSymbolAddress((void**)&wqkv16, g_wqkv16);
    cudaGetSymbolAddress((void**)&wo16,   g_wo16);

    dim3 blk(256);
    dim3 tb(32, 8);
    const int GEMM_SMEM  = 61440;
    const int FLASH_SMEM = 145664;
    cudaFuncSetAttribute(gemm_mma, cudaFuncAttributeMaxDynamicSharedMemorySize, GEMM_SMEM);
    cudaFuncSetAttribute(flash_mma, cudaFuncAttributeMaxDynamicSharedMemorySize, FLASH_SMEM);

    // index 3 = fused QKV gemm (ncu capture slot)
    {
        int n4 = WIN * HID / 4;   // only rows >= WIN are consumed by GEMM1
        split_kernel<<<(n4 + 255) / 256, blk>>>(x + (size_t)WIN * HID, xhi, xlo, n4);  // 0
    }
    splitT_qkv_kernel<<<dim3(QKVN / 32, HID / 32), tb>>>(wq, wk, wv);          // 1
    splitT_wo_kernel<<<dim3(HID / 32, QDIM / 32), tb>>>(wo);                   // 2
    gemm_mma<<<dim3(QKVN / 128, WIN / 128), blk, GEMM_SMEM>>>(                 // 3
        xhi, xlo, wqkv16, pqkv, WIN, QKVN, HID);

    // RoPE + operand prep for flash: Q split, K single, VT single
    invf_init_kernel<<<1, 128>>>();
    rope_split_kernel<<<WIN, 128>>>(0, NHQ, qshi, qslo);
    rope_split_kernel<<<WIN, 128>>>(QDIM, NKV, k16, (/*lo*/__half*)nullptr);
    vt_split_kernel<<<dim3(WIN / 32, DH / 32, NKV), tb>>>();

    // lowq rows: xsum -> vmean -> lowrow -> fill
    xsum_part_kernel<<<dim3(9, 16), blk>>>(x);
    xsum_comb_kernel<<<9, blk>>>();
    vmean_part_kernel<<<dim3(4, 8), blk>>>(wv);
    vmean_comb_kernel<<<4, blk>>>();
    lowout_part_kernel<<<dim3(9, 8), blk>>>(wo);
    lowout_comb_kernel<<<9, blk>>>();
    lowfill_kernel<<<(WIN * HID + 255) / 256, blk>>>(out);

    // Flash attention (q >= 2048)
    flash_mma<<<dim3(32, NHQ), blk, FLASH_SMEM>>>(
        qshi, qslo, k16, vt16, ahi, alo);

    // Output projection: high rows only
    gemm_mma<<<dim3(HID / 128, WIN / 128), blk, GEMM_SMEM>>>(
        ahi, alo, wo16, out + (size_t)WIN * HID, WIN, HID, QDIM);
}

// round 16
// speedup vs baseline: 1.6787x; 1.2551x over previous
#include <cuda_runtime.h>
#include <cuda_fp16.h>
#include <math.h>
#include <stdint.h>

#define LSEQ 4096
#define NHQ 8
#define NKV 4
#define DH 256
#define HID 2304
#define WIN 2048
#define QDIM (NHQ*DH)   /* 2048 */
#define KDIM (NKV*DH)   /* 1024 */
#define QKVN (QDIM + 2*KDIM)  /* 4096 fused N */

#define SCALEF 0.05892556509887896f   /* 288^-0.5 */
#define NEGC  (-1.0e9f)

// fused QKV projection output (rows = l - WIN, cols = [q|k|v])
static __device__ float g_qkv[(size_t)WIN * QKVN];
static __device__ float g_vmean[KDIM];
static __device__ float g_lowrow[HID];
static __device__ float g_invf[128];
static __device__ float g_xpart[16 * HID];
static __device__ float g_xsum[HID];
static __device__ float g_vpart[8 * KDIM];
static __device__ float g_lowpart[8 * HID];

// fp16 operands (x: rows >= WIN only, single-rounded)
static __device__ __half g_x16[(size_t)WIN * HID];
static __device__ __half g_a16[(size_t)WIN * QDIM];
// roped, compacted (rows = l - WIN); Q split, K single-rounded
static __device__ __half g_qhi[(size_t)WIN * QDIM];
static __device__ __half g_qlo[(size_t)WIN * QDIM];
static __device__ __half g_k16[(size_t)WIN * KDIM];
// V transposed per kv head, single-rounded: [hkv][d=256][k-WIN=2048]
static __device__ __half g_vt16[(size_t)NKV * DH * WIN];
// weights single-rounded fp16, transposed to [N][K] K-major
static __device__ __half g_wqkv16[(size_t)QKVN * HID];
static __device__ __half g_wo16[(size_t)HID * QDIM];

// ===========================================================================
// Helpers (base-target PTX only)
// ===========================================================================
__device__ __forceinline__ uint32_t smem_u32(const void* p) {
    uint32_t r;
    asm("{ .reg .u64 t; cvta.to.shared.u64 t, %1; cvt.u32.u64 %0, t; }"
        : "=r"(r) : "l"(p));
    return r;
}

#define CP_ASYNC16(dst, src) \
    asm volatile("cp.async.cg.shared.global [%0], [%1], 16;" \
                 :: "r"(dst), "l"(src) : "memory")
#define CP_COMMIT()  asm volatile("cp.async.commit_group;" ::: "memory")
#define CP_WAIT0()   asm volatile("cp.async.wait_group 0;" ::: "memory")
#define CP_WAIT1()   asm volatile("cp.async.wait_group 1;" ::: "memory")

#define LDSM4(R, addr) \
    asm volatile("ldmatrix.sync.aligned.m8n8.x4.shared.b16 {%0,%1,%2,%3}, [%4];" \
        : "=r"((R)[0]), "=r"((R)[1]), "=r"((R)[2]), "=r"((R)[3]) : "r"(addr))

#define MMA16(ACC, A, B) \
    asm volatile("mma.sync.aligned.m16n8k16.row.col.f32.f16.f16.f32 " \
        "{%0,%1,%2,%3}, {%4,%5,%6,%7}, {%8,%9}, {%0,%1,%2,%3};" \
        : "+f"((ACC)[0]), "+f"((ACC)[1]), "+f"((ACC)[2]), "+f"((ACC)[3]) \
        : "r"((A)[0]), "r"((A)[1]), "r"((A)[2]), "r"((A)[3]), \
          "r"((B)[0]), "r"((B)[1]))

__device__ __forceinline__ void split2h(float f, __half& h, __half& l)
{
    h = __float2half_rn(f);
    l = __float2half_rn(f - __half2float(h));
}

// ===========================================================================
// fp16 1-term MMA GEMM: C[M,N] = A16[M,K] @ B16[N,K]^T (fp32 out).
// CTA 128x128, BK=32, double-buffered. Stage: A@0, B@10240;
// stage stride 20480, 2 stages = 40960 B dynamic smem.
// ===========================================================================
__global__ __launch_bounds__(256) void gemm_mma1(
    const __half* __restrict__ A, const __half* __restrict__ B,
    float* __restrict__ C, int M, int N, int K)
{
    extern __shared__ char smdyn[];
    const uint32_t sbase = smem_u32(smdyn);
    const int tid  = threadIdx.x;
    const int warp = tid >> 5;
    const int lane = tid & 31;
    const int wm = warp >> 2;
    const int wn = warp & 3;
    const int row0 = blockIdx.y * 128;
    const int col0 = blockIdx.x * 128;

    const __half* gsrc[2] = { A + (size_t)row0 * K, B + (size_t)col0 * K };

    float acc[4][4][4];
#pragma unroll
    for (int a = 0; a < 4; a++)
#pragma unroll
        for (int b = 0; b < 4; b++)
#pragma unroll
            for (int c = 0; c < 4; c++) acc[a][b][c] = 0.0f;

    const int S = K >> 5;

#define GEMM1_COPY_SLAB(stoff, k0)                                           \
    do {                                                                     \
        _Pragma("unroll")                                                    \
        for (int i = 0; i < 4; i++) {                                        \
            int c = tid + (i << 8);                                          \
            int op = c >> 9, cc = c & 511;                                   \
            int row = cc >> 2, kc = cc & 3;                                  \
            uint32_t dst = sbase + (uint32_t)(stoff) +                       \
                           (uint32_t)(op * 10240 + row * 80 + kc * 16);      \
            const char* src = (const char*)(gsrc[op] + (size_t)row * K + (k0)) + kc * 16; \
            CP_ASYNC16(dst, src);                                            \
        }                                                                    \
    } while (0)

    GEMM1_COPY_SLAB(0, 0);
    CP_COMMIT();
    CP_WAIT0();
    __syncthreads();

    for (int s = 0; s < S; s++) {
        const int st = s & 1;
        if (s + 1 < S) {
            GEMM1_COPY_SLAB((st ^ 1) * 20480, (s + 1) << 5);
            CP_COMMIT();
        }

        const uint32_t base = sbase + (uint32_t)(st * 20480);
#pragma unroll
        for (int t = 0; t < 2; t++) {
            uint32_t af[4][4], bf[4][2];
#pragma unroll
            for (int mf = 0; mf < 4; mf++) {
                int r = wm * 64 + mf * 16 + (lane & 15);
                uint32_t ad = base + (uint32_t)(r * 80 + t * 32 + ((lane >> 4) << 4));
                LDSM4(af[mf], ad);
            }
#pragma unroll
            for (int g = 0; g < 2; g++) {
                int n = wn * 32 + g * 16 + (lane & 15);
                uint32_t bd = base + 10240u + (uint32_t)(n * 80 + t * 32 + ((lane >> 4) << 4));
                uint32_t h4[4];
                LDSM4(h4, bd);
                bf[2 * g][0]     = h4[0]; bf[2 * g][1]     = h4[2];
                bf[2 * g + 1][0] = h4[1]; bf[2 * g + 1][1] = h4[3];
            }
#pragma unroll
            for (int mf = 0; mf < 4; mf++)
#pragma unroll
                for (int nf = 0; nf < 4; nf++)
                    MMA16(acc[mf][nf], af[mf], bf[nf]);
        }
        CP_WAIT0();
        __syncthreads();
    }

    const int qr = lane >> 2;
    const int qc = (lane & 3) * 2;
#pragma unroll
    for (int mf = 0; mf < 4; mf++)
#pragma unroll
        for (int nf = 0; nf < 4; nf++) {
            int r = row0 + wm * 64 + mf * 16 + qr;
            int cI = col0 + wn * 32 + nf * 8 + qc;
            float2 v0 = make_float2(acc[mf][nf][0], acc[mf][nf][1]);
            float2 v1 = make_float2(acc[mf][nf][2], acc[mf][nf][3]);
            *(float2*)(C + (size_t)r * N + cI)       = v0;
            *(float2*)(C + (size_t)(r + 8) * N + cI) = v1;
        }
}

// ===========================================================================
// fp16 conversions
// ===========================================================================
__global__ void cvt16_kernel(const float* __restrict__ src,
                             __half* __restrict__ dst, int n4)
{
    int i = blockIdx.x * blockDim.x + threadIdx.x;
    if (i >= n4) return;
    float4 v = *(const float4*)(src + (size_t)i * 4);
    *(__half2*)(dst + (size_t)i * 4)     = __halves2half2(__float2half_rn(v.x), __float2half_rn(v.y));
    *(__half2*)(dst + (size_t)i * 4 + 2) = __halves2half2(__float2half_rn(v.z), __float2half_rn(v.w));
}

// Fused transposing single-round of wq|wk|wv into g_wqkv16 [4096][2304]
__global__ void splitT_qkv_kernel(const float* __restrict__ wq,
                                  const float* __restrict__ wk,
                                  const float* __restrict__ wv)
{
    __shared__ float t[32][33];
    const int n0 = blockIdx.x * 32;
    const int k0 = blockIdx.y * 32;
    const int tx = threadIdx.x, ty = threadIdx.y;

    const float* W;
    int Nsrc, nb;
    if (n0 < QDIM)             { W = wq; Nsrc = QDIM; nb = n0; }
    else if (n0 < QDIM + KDIM) { W = wk; Nsrc = KDIM; nb = n0 - QDIM; }
    else                       { W = wv; Nsrc = KDIM; nb = n0 - QDIM - KDIM; }

#pragma unroll
    for (int j = 0; j < 4; j++)
        t[ty + j * 8][tx] = W[(size_t)(k0 + ty + j * 8) * Nsrc + nb + tx];
    __syncthreads();
#pragma unroll
    for (int j = 0; j < 4; j++) {
        float v = t[tx][ty + j * 8];
        g_wqkv16[(size_t)(n0 + ty + j * 8) * HID + k0 + tx] = __float2half_rn(v);
    }
}

__global__ void splitT_wo_kernel(const float* __restrict__ W)
{
    __shared__ float t[32][33];
    const int n0 = blockIdx.x * 32;
    const int k0 = blockIdx.y * 32;
    const int tx = threadIdx.x, ty = threadIdx.y;
#pragma unroll
    for (int j = 0; j < 4; j++)
        t[ty + j * 8][tx] = W[(size_t)(k0 + ty + j * 8) * HID + n0 + tx];
    __syncthreads();
#pragma unroll
    for (int j = 0; j < 4; j++) {
        float v = t[tx][ty + j * 8];
        g_wo16[(size_t)(n0 + ty + j * 8) * QDIM + k0 + tx] = __float2half_rn(v);
    }
}

// ===========================================================================
// RoPE: invf table once, trig inline
// ===========================================================================
__global__ void invf_init_kernel()
{
    int i = threadIdx.x;
    double ex = (double)(2 * i) / 256.0;
    float pf = (float)pow(10000.0, ex);
    g_invf[i] = __fdiv_rn(1.0f, pf);
}

// RoPE + fp16 conversion; lo == nullptr -> single-rounded only
__global__ void rope_split_kernel(int coloff, int nheads,
                                  __half* __restrict__ hi,
                                  __half* __restrict__ lo)
{
    int row = blockIdx.x;
    int l = WIN + row;
    int i = threadIdx.x;
    float ang = (float)l * g_invf[i];
    double a  = (double)ang;
    double kq = rint(a * 0.15915494309189535);
    double r  = fma(-kq, 6.283185307179586, a);
    float s, c;
    __sincosf((float)r, &s, &c);
    int nd = nheads * DH;
    for (int h = 0; h < nheads; h++) {
        size_t base = (size_t)row * QKVN + coloff + (size_t)h * DH;
        float x1 = g_qkv[base + i];
        float x2 = g_qkv[base + i + 128];
        float y1 = x1 * c - x2 * s;
        float y2 = x2 * c + x1 * s;
        size_t o = (size_t)row * nd + (size_t)h * DH;
        __half h1 = __float2half_rn(y1);
        __half h2 = __float2half_rn(y2);
        hi[o + i]       = h1;
        hi[o + i + 128] = h2;
        if (lo) {
            lo[o + i]       = __float2half_rn(y1 - __half2float(h1));
            lo[o + i + 128] = __float2half_rn(y2 - __half2float(h2));
        }
    }
}

// V transpose, single-rounded fp16
__global__ void vt_split_kernel()
{
    __shared__ float t[32][33];
    const int k0  = blockIdx.x * 32;
    const int d0  = blockIdx.y * 32;
    const int hkv = blockIdx.z;
    const int tx = threadIdx.x, ty = threadIdx.y;
#pragma unroll
    for (int j = 0; j < 4; j++)
        t[ty + j * 8][tx] = g_qkv[(size_t)(k0 + ty + j * 8) * QKVN
                                  + QDIM + KDIM + hkv * DH + d0 + tx];
    __syncthreads();
#pragma unroll
    for (int j = 0; j < 4; j++) {
        float v = t[tx][ty + j * 8];
        size_t o = (size_t)hkv * DH * WIN + (size_t)(d0 + ty + j * 8) * WIN + k0 + tx;
        g_vt16[o] = __float2half_rn(v);
    }
}

// ===========================================================================
// lowq path via linearity: vmean = (sum_l x_l) @ wv / 4096  (full fp32)
// ===========================================================================
__global__ void xsum_part_kernel(const float* __restrict__ x)
{
    int j = blockIdx.x * 256 + threadIdx.x;
    if (j >= HID) return;
    int p = blockIdx.y;
    float s = 0.0f;
    for (int l = p * 256; l < (p + 1) * 256; l++)
        s += x[(size_t)l * HID + j];
    g_xpart[p * HID + j] = s;
}
__global__ void xsum_comb_kernel()
{
    int j = blockIdx.x * 256 + threadIdx.x;
    if (j >= HID) return;
    float s = 0.0f;
#pragma unroll
    for (int p = 0; p < 16; p++) s += g_xpart[p * HID + j];
    g_xsum[j] = s;
}
__global__ void vmean_part_kernel(const float* __restrict__ wv)
{
    int d = blockIdx.x * 256 + threadIdx.x;
    if (d >= KDIM) return;
    int p = blockIdx.y;
    float s = 0.0f;
    for (int i = p * 288; i < (p + 1) * 288; i++)
        s = fmaf(g_xsum[i], wv[(size_t)i * KDIM + d], s);
    g_vpart[p * KDIM + d] = s;
}
__global__ void vmean_comb_kernel()
{
    int d = blockIdx.x * 256 + threadIdx.x;
    if (d >= KDIM) return;
    float s = 0.0f;
#pragma unroll
    for (int p = 0; p < 8; p++) s += g_vpart[p * KDIM + d];
    g_vmean[d] = s * (1.0f / 4096.0f);
}
__global__ void lowout_part_kernel(const float* __restrict__ wo)
{
    int j = blockIdx.x * 256 + threadIdx.x;
    if (j >= HID) return;
    int p = blockIdx.y;
    float s = 0.0f;
    for (int i = p * 256; i < (p + 1) * 256; i++) {
        int h = i >> 8, d = i & 255;
        float r = g_vmean[(h >> 1) * 256 + d];
        s = fmaf(r, wo[(size_t)i * HID + j], s);
    }
    g_lowpart[p * HID + j] = s;
}
__global__ void lowout_comb_kernel()
{
    int j = blockIdx.x * 256 + threadIdx.x;
    if (j >= HID) return;
    float s = 0.0f;
#pragma unroll
    for (int p = 0; p < 8; p++) s += g_lowpart[p * HID + j];
    g_lowrow[j] = s;
}
__global__ void lowfill_kernel(float* __restrict__ out)
{
    int idx = blockIdx.x * blockDim.x + threadIdx.x;
    if (idx >= WIN * HID) return;
    out[idx] = g_lowrow[idx % HID];
}

// ===========================================================================
// Fast accurate softcap: tanh via MUFU-backed __expf
// ===========================================================================
__device__ __forceinline__ float softcap50(float s)
{
    float x = __fdiv_rn(s * SCALEF, 50.0f);
    x = fminf(fmaxf(x, -15.0f), 15.0f);
    float e = __expf(2.0f * x);
    return 50.0f * __fdiv_rn(e - 1.0f, e + 1.0f);
}

// ===========================================================================
// Tensor-core flash attention (q >= 2048), pipelined (validated R15 shell).
// QK 2-term (Q split, K single); PV 2-term (P split, V single).
// Epilogue writes single-rounded O (wo gemm is 1-term).
// ===========================================================================
__global__ __launch_bounds__(256) void flash_mma(
    const __half* __restrict__ Qhi, const __half* __restrict__ Qlo,
    const __half* __restrict__ K16,
    const __half* __restrict__ Vt16,
    __half* __restrict__ O16)
{
    extern __shared__ char dsm[];
    const uint32_t sb = smem_u32(dsm);
    float* SS  = (float*)(dsm + 125440);
    float* m_s = (float*)(dsm + 144896);
    float* l_s = (float*)(dsm + 145152);
    float* c_s = (float*)(dsm + 145408);

    const int tid  = threadIdx.x;
    const int warp = tid >> 5;
    const int lane = tid & 31;
    const int h    = blockIdx.y;
    const int hkv  = h >> 1;
    const int it   = 31 - (int)blockIdx.x;
    const int q0r  = it * 64;
    const int nk   = 2 * it + 2;

    const size_t vtbase_g = (size_t)hkv * DH * WIN;

#pragma unroll
    for (int i = 0; i < 16; i++) {
        int c = tid + (i << 8);
        int op = c >> 11, cc = c & 2047;
        int row = cc >> 5, ch = cc & 31;
        uint32_t dst = sb + (uint32_t)(op * 33792 + row * 528 + ch * 16);
        const char* src = (const char*)((op ? Qlo : Qhi)
                          + (size_t)(q0r + row) * QDIM + h * DH) + ch * 16;
        CP_ASYNC16(dst, src);
    }
#pragma unroll
    for (int i = 0; i < 4; i++) {
        int c = tid + (i << 8);
        int row = c >> 5, ch = c & 31;
        uint32_t dst = sb + 67584u + (uint32_t)(row * 528 + ch * 16);
        const char* src = (const char*)(K16 + (size_t)row * KDIM + hkv * DH) + ch * 16;
        CP_ASYNC16(dst, src);
    }
#pragma unroll
    for (int i = 0; i < 4; i++) {
        int c = tid + (i << 8);
        int row = c >> 2, ch = c & 3;
        uint32_t dst = sb + 84480u + (uint32_t)(row * 80 + ch * 16);
        const char* src = (const char*)(Vt16 + vtbase_g + (size_t)row * WIN) + ch * 16;
        CP_ASYNC16(dst, src);
    }
    CP_COMMIT();

    if (tid < 64) { m_s[tid] = -INFINITY; l_s[tid] = 0.0f; }

    float o[4][4][4];
#pragma unroll
    for (int a = 0; a < 4; a++)
#pragma unroll
        for (int b = 0; b < 4; b++)
#pragma unroll
            for (int c = 0; c < 4; c++) o[a][b][c] = 0.0f;

    const int wm = warp >> 1;
    const int wn = warp & 1;
    const int qr = lane >> 2, qc = (lane & 3) * 2;

    for (int t = 0; t < nk; t++) {
        if (t + 1 < nk) {
            const int k1 = (t + 1) * 32;
            const uint32_t vtoff = 84480u + (uint32_t)(((t + 1) & 1) * 20480);
#pragma unroll
            for (int i = 0; i < 4; i++) {
                int c = tid + (i << 8);
                int row = c >> 2, ch = c & 3;
                uint32_t dst = sb + vtoff + (uint32_t)(row * 80 + ch * 16);
                const char* src = (const char*)(Vt16 + vtbase_g + (size_t)row * WIN + k1) + ch * 16;
                CP_ASYNC16(dst, src);
            }
            CP_COMMIT();
            CP_WAIT1();
        } else {
            CP_WAIT0();
        }
        __syncthreads();

        const int k0r = t * 32;

        float s[2][4];
#pragma unroll
        for (int nf = 0; nf < 2; nf++)
#pragma unroll
            for (int e = 0; e < 4; e++) s[nf][e] = 0.0f;

#pragma unroll
        for (int ds = 0; ds < 16; ds++) {
            uint32_t ah[4], al[4], kh4[4];
            uint32_t qa = sb + (uint32_t)((wm * 16 + (lane & 15)) * 528
                           + ds * 32 + ((lane >> 4) << 4));
            LDSM4(ah, qa);
            LDSM4(al, qa + 33792);
            uint32_t ka = sb + 67584u + (uint32_t)((wn * 16 + (lane & 15)) * 528
                           + ds * 32 + ((lane >> 4) << 4));
            LDSM4(kh4, ka);
            uint32_t bh0[2] = {kh4[0], kh4[2]}, bh1[2] = {kh4[1], kh4[3]};
            MMA16(s[0], ah, bh0); MMA16(s[1], ah, bh1);
            MMA16(s[0], al, bh0); MMA16(s[1], al, bh1);
        }

#pragma unroll
        for (int nf = 0; nf < 2; nf++)
#pragma unroll
            for (int e = 0; e < 4; e++) {
                int r = wm * 16 + qr + ((e >> 1) * 8);
                int cI = wn * 16 + nf * 8 + qc + (e & 1);
                float v = softcap50(s[nf][e]);
                if (k0r + cI > q0r + r) v = NEGC;
                SS[r * 36 + cI] = v;
            }
        __syncthreads();

        if (t + 1 < nk) {
            const int k1 = (t + 1) * 32;
#pragma unroll
            for (int i = 0; i < 4; i++) {
                int c = tid + (i << 8);
                int row = c >> 5, ch = c & 31;
                uint32_t dst = sb + 67584u + (uint32_t)(row * 528 + ch * 16);
                const char* src = (const char*)(K16 + (size_t)(k1 + row) * KDIM + hkv * DH) + ch * 16;
                CP_ASYNC16(dst, src);
            }
            CP_COMMIT();
        }

        {
            int r = tid >> 2, sub = tid & 3;
            const float* rp = SS + r * 36 + sub * 8;
            float mo = m_s[r];
            float v[8];
#pragma unroll
            for (int j = 0; j < 8; j++) v[j] = rp[j];
            float mx8 = v[0];
#pragma unroll
            for (int j = 1; j < 8; j++) mx8 = fmaxf(mx8, v[j]);
            mx8 = fmaxf(mx8, __shfl_xor_sync(0xFFFFFFFFu, mx8, 1));
            mx8 = fmaxf(mx8, __shfl_xor_sync(0xFFFFFFFFu, mx8, 2));
            float mx = fmaxf(mo, mx8);
            float corr = expf(mo - mx);
            __half* ph = (__half*)(dsm + 134656) + r * 40 + sub * 8;
            __half* pl = (__half*)(dsm + 139776) + r * 40 + sub * 8;
            float sum = 0.0f;
#pragma unroll
            for (int j = 0; j < 8; j++) {
                float p = expf(v[j] - mx);
                sum += p;
                __half hh, hl;
                split2h(p, hh, hl);
                ph[j] = hh;
                pl[j] = hl;
            }
            sum += __shfl_xor_sync(0xFFFFFFFFu, sum, 1);
            sum += __shfl_xor_sync(0xFFFFFFFFu, sum, 2);
            if (sub == 0) {
                m_s[r] = mx;
                l_s[r] = fmaf(l_s[r], corr, sum);
                c_s[r] = corr;
            }
        }
        __syncthreads();

#pragma unroll
        for (int mf = 0; mf < 4; mf++) {
            float c0 = c_s[mf * 16 + qr];
            float c1 = c_s[mf * 16 + qr + 8];
#pragma unroll
            for (int nf = 0; nf < 4; nf++) {
                o[mf][nf][0] *= c0; o[mf][nf][1] *= c0;
                o[mf][nf][2] *= c1; o[mf][nf][3] *= c1;
            }
        }

        const uint32_t vtb = sb + 84480u + (uint32_t)((t & 1) * 20480);
#pragma unroll
        for (int ks = 0; ks < 2; ks++) {
            uint32_t aph[4][4], apl[4][4], bh[4][2];
#pragma unroll
            for (int mf = 0; mf < 4; mf++) {
                uint32_t pa = sb + 134656u + (uint32_t)((mf * 16 + (lane & 15)) * 80
                               + ks * 32 + ((lane >> 4) << 4));
                LDSM4(aph[mf], pa);
                LDSM4(apl[mf], pa + 5120);
            }
#pragma unroll
            for (int g = 0; g < 2; g++) {
                uint32_t va = vtb + (uint32_t)((warp * 32 + g * 16 + (lane & 15)) * 80
                               + ks * 32 + ((lane >> 4) << 4));
                uint32_t vh4[4];
                LDSM4(vh4, va);
                bh[2 * g][0]     = vh4[0]; bh[2 * g][1]     = vh4[2];
                bh[2 * g + 1][0] = vh4[1]; bh[2 * g + 1][1] = vh4[3];
            }
#pragma unroll
            for (int mf = 0; mf < 4; mf++)
#pragma unroll
                for (int nf = 0; nf < 4; nf++)
                    MMA16(o[mf][nf], aph[mf], bh[nf]);
#pragma unroll
            for (int mf = 0; mf < 4; mf++)
#pragma unroll
                for (int nf = 0; nf < 4; nf++)
                    MMA16(o[mf][nf], apl[mf], bh[nf]);
        }
        __syncthreads();
    }

    // epilogue: single-rounded fp16 output
#pragma unroll
    for (int mf = 0; mf < 4; mf++) {
        float li0 = l_s[mf * 16 + qr];
        float li1 = l_s[mf * 16 + qr + 8];
        int r0 = q0r + mf * 16 + qr;
#pragma unroll
        for (int nf = 0; nf < 4; nf++) {
            int dcol = warp * 32 + nf * 8 + qc;
            size_t o0 = (size_t)r0 * QDIM + h * DH + dcol;
            size_t o1 = (size_t)(r0 + 8) * QDIM + h * DH + dcol;
            *(__half2*)(O16 + o0) = __halves2half2(
                __float2half_rn(__fdiv_rn(o[mf][nf][0], li0)),
                __float2half_rn(__fdiv_rn(o[mf][nf][1], li0)));
            *(__half2*)(O16 + o1) = __halves2half2(
                __float2half_rn(__fdiv_rn(o[mf][nf][2], li1)),
                __float2half_rn(__fdiv_rn(o[mf][nf][3], li1)));
        }
    }
}

// ===========================================================================
extern "C" void kernel_launch(void* const* d_in, const int* in_sizes, int n_in,
                              void* d_out, int out_size)
{
    const float* x  = (const float*)d_in[0];
    const float* wq = (const float*)d_in[2];
    const float* wk = (const float*)d_in[3];
    const float* wv = (const float*)d_in[4];
    const float* wo = (const float*)d_in[5];
    float* out = (float*)d_out;

    float* pqkv;
    cudaGetSymbolAddress((void**)&pqkv, g_qkv);
    __half *x16, *a16, *qshi, *qslo, *k16, *vt16, *wqkv16, *wo16;
    cudaGetSymbolAddress((void**)&x16,    g_x16);
    cudaGetSymbolAddress((void**)&a16,    g_a16);
    cudaGetSymbolAddress((void**)&qshi,   g_qhi);
    cudaGetSymbolAddress((void**)&qslo,   g_qlo);
    cudaGetSymbolAddress((void**)&k16,    g_k16);
    cudaGetSymbolAddress((void**)&vt16,   g_vt16);
    cudaGetSymbolAddress((void**)&wqkv16, g_wqkv16);
    cudaGetSymbolAddress((void**)&wo16,   g_wo16);

    dim3 blk(256);
    dim3 tb(32, 8);
    const int GEMM_SMEM  = 40960;
    const int FLASH_SMEM = 145664;
    cudaFuncSetAttribute(gemm_mma1, cudaFuncAttributeMaxDynamicSharedMemorySize, GEMM_SMEM);
    cudaFuncSetAttribute(flash_mma, cudaFuncAttributeMaxDynamicSharedMemorySize, FLASH_SMEM);

    // index 3 = fused QKV gemm (ncu capture slot)
    {
        int n4 = WIN * HID / 4;
        cvt16_kernel<<<(n4 + 255) / 256, blk>>>(x + (size_t)WIN * HID, x16, n4);  // 0
    }
    splitT_qkv_kernel<<<dim3(QKVN / 32, HID / 32), tb>>>(wq, wk, wv);          // 1
    splitT_wo_kernel<<<dim3(HID / 32, QDIM / 32), tb>>>(wo);                   // 2
    gemm_mma1<<<dim3(QKVN / 128, WIN / 128), blk, GEMM_SMEM>>>(                // 3
        x16, wqkv16, pqkv, WIN, QKVN, HID);

    // RoPE + operand prep for flash: Q split, K single, VT single
    invf_init_kernel<<<1, 128>>>();
    rope_split_kernel<<<WIN, 128>>>(0, NHQ, qshi, qslo);
    rope_split_kernel<<<WIN, 128>>>(QDIM, NKV, k16, (__half*)nullptr);
    vt_split_kernel<<<dim3(WIN / 32, DH / 32, NKV), tb>>>();

    // lowq rows: xsum -> vmean -> lowrow -> fill (full fp32, exact)
    xsum_part_kernel<<<dim3(9, 16), blk>>>(x);
    xsum_comb_kernel<<<9, blk>>>();
    vmean_part_kernel<<<dim3(4, 8), blk>>>(wv);
    vmean_comb_kernel<<<4, blk>>>();
    lowout_part_kernel<<<dim3(9, 8), blk>>>(wo);
    lowout_comb_kernel<<<9, blk>>>();
    lowfill_kernel<<<(WIN * HID + 255) / 256, blk>>>(out);

    // Flash attention (q >= 2048); writes single-rounded a16
    flash_mma<<<dim3(32, NHQ), blk, FLASH_SMEM>>>(
        qshi, qslo, k16, vt16, a16);

    // Output projection: 1-term
    gemm_mma1<<<dim3(HID / 128, WIN / 128), blk, GEMM_SMEM>>>(
        a16, wo16, out + (size_t)WIN * HID, WIN, HID, QDIM);
}

// round 17
// speedup vs baseline: 1.9012x; 1.1325x over previous
#include <cuda_runtime.h>
#include <cuda_fp16.h>
#include <math.h>
#include <stdint.h>

#define LSEQ 4096
#define NHQ 8
#define NKV 4
#define DH 256
#define HID 2304
#define WIN 2048
#define QDIM (NHQ*DH)   /* 2048 */
#define KDIM (NKV*DH)   /* 1024 */
#define QKVN (QDIM + 2*KDIM)  /* 4096 fused N */

#define SCALEF 0.05892556509887896f   /* 288^-0.5 */
#define NEGC  (-1.0e9f)

// fused QKV projection output (rows = l - WIN, cols = [q|k|v])
static __device__ float g_qkv[(size_t)WIN * QKVN];
static __device__ float g_vmean[KDIM];
static __device__ float g_lowrow[HID];
static __device__ float g_invf[128];
static __device__ float g_xpart[16 * HID];
static __device__ float g_xsum[HID];
static __device__ float g_vpart[8 * KDIM];
static __device__ float g_lowpart[8 * HID];

// fp16 operands (all single-rounded now)
static __device__ __half g_x16[(size_t)WIN * HID];
static __device__ __half g_a16[(size_t)WIN * QDIM];
static __device__ __half g_q16[(size_t)WIN * QDIM];
static __device__ __half g_k16[(size_t)WIN * KDIM];
// V transposed per kv head: [hkv][d=256][k-WIN=2048]
static __device__ __half g_vt16[(size_t)NKV * DH * WIN];
// weights fp16, transposed to [N][K] K-major
static __device__ __half g_wqkv16[(size_t)QKVN * HID];
static __device__ __half g_wo16[(size_t)HID * QDIM];

// ===========================================================================
// Helpers (base-target PTX only)
// ===========================================================================
__device__ __forceinline__ uint32_t smem_u32(const void* p) {
    uint32_t r;
    asm("{ .reg .u64 t; cvta.to.shared.u64 t, %1; cvt.u32.u64 %0, t; }"
        : "=r"(r) : "l"(p));
    return r;
}

#define CP_ASYNC16(dst, src) \
    asm volatile("cp.async.cg.shared.global [%0], [%1], 16;" \
                 :: "r"(dst), "l"(src) : "memory")
#define CP_COMMIT()  asm volatile("cp.async.commit_group;" ::: "memory")
#define CP_WAIT0()   asm volatile("cp.async.wait_group 0;" ::: "memory")
#define CP_WAIT1()   asm volatile("cp.async.wait_group 1;" ::: "memory")

#define LDSM4(R, addr) \
    asm volatile("ldmatrix.sync.aligned.m8n8.x4.shared.b16 {%0,%1,%2,%3}, [%4];" \
        : "=r"((R)[0]), "=r"((R)[1]), "=r"((R)[2]), "=r"((R)[3]) : "r"(addr))

#define MMA16(ACC, A, B) \
    asm volatile("mma.sync.aligned.m16n8k16.row.col.f32.f16.f16.f32 " \
        "{%0,%1,%2,%3}, {%4,%5,%6,%7}, {%8,%9}, {%0,%1,%2,%3};" \
        : "+f"((ACC)[0]), "+f"((ACC)[1]), "+f"((ACC)[2]), "+f"((ACC)[3]) \
        : "r"((A)[0]), "r"((A)[1]), "r"((A)[2]), "r"((A)[3]), \
          "r"((B)[0]), "r"((B)[1]))

// ===========================================================================
// fp16 1-term MMA GEMM (validated R16): C = A16 @ B16^T, fp32 out.
// CTA 128x128, BK=32, double-buffered. Stage: A@0, B@10240; stride 20480.
// ===========================================================================
__global__ __launch_bounds__(256) void gemm_mma1(
    const __half* __restrict__ A, const __half* __restrict__ B,
    float* __restrict__ C, int M, int N, int K)
{
    extern __shared__ char smdyn[];
    const uint32_t sbase = smem_u32(smdyn);
    const int tid  = threadIdx.x;
    const int warp = tid >> 5;
    const int lane = tid & 31;
    const int wm = warp >> 2;
    const int wn = warp & 3;
    const int row0 = blockIdx.y * 128;
    const int col0 = blockIdx.x * 128;

    const __half* gsrc[2] = { A + (size_t)row0 * K, B + (size_t)col0 * K };

    float acc[4][4][4];
#pragma unroll
    for (int a = 0; a < 4; a++)
#pragma unroll
        for (int b = 0; b < 4; b++)
#pragma unroll
            for (int c = 0; c < 4; c++) acc[a][b][c] = 0.0f;

    const int S = K >> 5;

#define GEMM1_COPY_SLAB(stoff, k0)                                           \
    do {                                                                     \
        _Pragma("unroll")                                                    \
        for (int i = 0; i < 4; i++) {                                        \
            int c = tid + (i << 8);                                          \
            int op = c >> 9, cc = c & 511;                                   \
            int row = cc >> 2, kc = cc & 3;                                  \
            uint32_t dst = sbase + (uint32_t)(stoff) +                       \
                           (uint32_t)(op * 10240 + row * 80 + kc * 16);      \
            const char* src = (const char*)(gsrc[op] + (size_t)row * K + (k0)) + kc * 16; \
            CP_ASYNC16(dst, src);                                            \
        }                                                                    \
    } while (0)

    GEMM1_COPY_SLAB(0, 0);
    CP_COMMIT();
    CP_WAIT0();
    __syncthreads();

    for (int s = 0; s < S; s++) {
        const int st = s & 1;
        if (s + 1 < S) {
            GEMM1_COPY_SLAB((st ^ 1) * 20480, (s + 1) << 5);
            CP_COMMIT();
        }

        const uint32_t base = sbase + (uint32_t)(st * 20480);
#pragma unroll
        for (int t = 0; t < 2; t++) {
            uint32_t af[4][4], bf[4][2];
#pragma unroll
            for (int mf = 0; mf < 4; mf++) {
                int r = wm * 64 + mf * 16 + (lane & 15);
                uint32_t ad = base + (uint32_t)(r * 80 + t * 32 + ((lane >> 4) << 4));
                LDSM4(af[mf], ad);
            }
#pragma unroll
            for (int g = 0; g < 2; g++) {
                int n = wn * 32 + g * 16 + (lane & 15);
                uint32_t bd = base + 10240u + (uint32_t)(n * 80 + t * 32 + ((lane >> 4) << 4));
                uint32_t h4[4];
                LDSM4(h4, bd);
                bf[2 * g][0]     = h4[0]; bf[2 * g][1]     = h4[2];
                bf[2 * g + 1][0] = h4[1]; bf[2 * g + 1][1] = h4[3];
            }
#pragma unroll
            for (int mf = 0; mf < 4; mf++)
#pragma unroll
                for (int nf = 0; nf < 4; nf++)
                    MMA16(acc[mf][nf], af[mf], bf[nf]);
        }
        CP_WAIT0();
        __syncthreads();
    }

    const int qr = lane >> 2;
    const int qc = (lane & 3) * 2;
#pragma unroll
    for (int mf = 0; mf < 4; mf++)
#pragma unroll
        for (int nf = 0; nf < 4; nf++) {
            int r = row0 + wm * 64 + mf * 16 + qr;
            int cI = col0 + wn * 32 + nf * 8 + qc;
            float2 v0 = make_float2(acc[mf][nf][0], acc[mf][nf][1]);
            float2 v1 = make_float2(acc[mf][nf][2], acc[mf][nf][3]);
            *(float2*)(C + (size_t)r * N + cI)       = v0;
            *(float2*)(C + (size_t)(r + 8) * N + cI) = v1;
        }
}

// ===========================================================================
// fp16 conversions
// ===========================================================================
__global__ void cvt16_kernel(const float* __restrict__ src,
                             __half* __restrict__ dst, int n4)
{
    int i = blockIdx.x * blockDim.x + threadIdx.x;
    if (i >= n4) return;
    float4 v = *(const float4*)(src + (size_t)i * 4);
    *(__half2*)(dst + (size_t)i * 4)     = __halves2half2(__float2half_rn(v.x), __float2half_rn(v.y));
    *(__half2*)(dst + (size_t)i * 4 + 2) = __halves2half2(__float2half_rn(v.z), __float2half_rn(v.w));
}

__global__ void splitT_qkv_kernel(const float* __restrict__ wq,
                                  const float* __restrict__ wk,
                                  const float* __restrict__ wv)
{
    __shared__ float t[32][33];
    const int n0 = blockIdx.x * 32;
    const int k0 = blockIdx.y * 32;
    const int tx = threadIdx.x, ty = threadIdx.y;

    const float* W;
    int Nsrc, nb;
    if (n0 < QDIM)             { W = wq; Nsrc = QDIM; nb = n0; }
    else if (n0 < QDIM + KDIM) { W = wk; Nsrc = KDIM; nb = n0 - QDIM; }
    else                       { W = wv; Nsrc = KDIM; nb = n0 - QDIM - KDIM; }

#pragma unroll
    for (int j = 0; j < 4; j++)
        t[ty + j * 8][tx] = W[(size_t)(k0 + ty + j * 8) * Nsrc + nb + tx];
    __syncthreads();
#pragma unroll
    for (int j = 0; j < 4; j++) {
        float v = t[tx][ty + j * 8];
        g_wqkv16[(size_t)(n0 + ty + j * 8) * HID + k0 + tx] = __float2half_rn(v);
    }
}

__global__ void splitT_wo_kernel(const float* __restrict__ W)
{
    __shared__ float t[32][33];
    const int n0 = blockIdx.x * 32;
    const int k0 = blockIdx.y * 32;
    const int tx = threadIdx.x, ty = threadIdx.y;
#pragma unroll
    for (int j = 0; j < 4; j++)
        t[ty + j * 8][tx] = W[(size_t)(k0 + ty + j * 8) * HID + n0 + tx];
    __syncthreads();
#pragma unroll
    for (int j = 0; j < 4; j++) {
        float v = t[tx][ty + j * 8];
        g_wo16[(size_t)(n0 + ty + j * 8) * QDIM + k0 + tx] = __float2half_rn(v);
    }
}

// ===========================================================================
// RoPE: invf table once, trig inline; fp16 single-rounded output
// ===========================================================================
__global__ void invf_init_kernel()
{
    int i = threadIdx.x;
    double ex = (double)(2 * i) / 256.0;
    float pf = (float)pow(10000.0, ex);
    g_invf[i] = __fdiv_rn(1.0f, pf);
}

__global__ void rope_cvt_kernel(int coloff, int nheads, __half* __restrict__ dst)
{
    int row = blockIdx.x;
    int l = WIN + row;
    int i = threadIdx.x;
    float ang = (float)l * g_invf[i];
    double a  = (double)ang;
    double kq = rint(a * 0.15915494309189535);
    double r  = fma(-kq, 6.283185307179586, a);
    float s, c;
    __sincosf((float)r, &s, &c);
    int nd = nheads * DH;
    for (int h = 0; h < nheads; h++) {
        size_t base = (size_t)row * QKVN + coloff + (size_t)h * DH;
        float x1 = g_qkv[base + i];
        float x2 = g_qkv[base + i + 128];
        size_t o = (size_t)row * nd + (size_t)h * DH;
        dst[o + i]       = __float2half_rn(x1 * c - x2 * s);
        dst[o + i + 128] = __float2half_rn(x2 * c + x1 * s);
    }
}

__global__ void vt_split_kernel()
{
    __shared__ float t[32][33];
    const int k0  = blockIdx.x * 32;
    const int d0  = blockIdx.y * 32;
    const int hkv = blockIdx.z;
    const int tx = threadIdx.x, ty = threadIdx.y;
#pragma unroll
    for (int j = 0; j < 4; j++)
        t[ty + j * 8][tx] = g_qkv[(size_t)(k0 + ty + j * 8) * QKVN
                                  + QDIM + KDIM + hkv * DH + d0 + tx];
    __syncthreads();
#pragma unroll
    for (int j = 0; j < 4; j++) {
        float v = t[tx][ty + j * 8];
        size_t o = (size_t)hkv * DH * WIN + (size_t)(d0 + ty + j * 8) * WIN + k0 + tx;
        g_vt16[o] = __float2half_rn(v);
    }
}

// ===========================================================================
// lowq path via linearity: vmean = (sum_l x_l) @ wv / 4096  (full fp32)
// ===========================================================================
__global__ void xsum_part_kernel(const float* __restrict__ x)
{
    int j = blockIdx.x * 256 + threadIdx.x;
    if (j >= HID) return;
    int p = blockIdx.y;
    float s = 0.0f;
    for (int l = p * 256; l < (p + 1) * 256; l++)
        s += x[(size_t)l * HID + j];
    g_xpart[p * HID + j] = s;
}
__global__ void xsum_comb_kernel()
{
    int j = blockIdx.x * 256 + threadIdx.x;
    if (j >= HID) return;
    float s = 0.0f;
#pragma unroll
    for (int p = 0; p < 16; p++) s += g_xpart[p * HID + j];
    g_xsum[j] = s;
}
__global__ void vmean_part_kernel(const float* __restrict__ wv)
{
    int d = blockIdx.x * 256 + threadIdx.x;
    if (d >= KDIM) return;
    int p = blockIdx.y;
    float s = 0.0f;
    for (int i = p * 288; i < (p + 1) * 288; i++)
        s = fmaf(g_xsum[i], wv[(size_t)i * KDIM + d], s);
    g_vpart[p * KDIM + d] = s;
}
__global__ void vmean_comb_kernel()
{
    int d = blockIdx.x * 256 + threadIdx.x;
    if (d >= KDIM) return;
    float s = 0.0f;
#pragma unroll
    for (int p = 0; p < 8; p++) s += g_vpart[p * KDIM + d];
    g_vmean[d] = s * (1.0f / 4096.0f);
}
__global__ void lowout_part_kernel(const float* __restrict__ wo)
{
    int j = blockIdx.x * 256 + threadIdx.x;
    if (j >= HID) return;
    int p = blockIdx.y;
    float s = 0.0f;
    for (int i = p * 256; i < (p + 1) * 256; i++) {
        int h = i >> 8, d = i & 255;
        float r = g_vmean[(h >> 1) * 256 + d];
        s = fmaf(r, wo[(size_t)i * HID + j], s);
    }
    g_lowpart[p * HID + j] = s;
}
__global__ void lowout_comb_kernel()
{
    int j = blockIdx.x * 256 + threadIdx.x;
    if (j >= HID) return;
    float s = 0.0f;
#pragma unroll
    for (int p = 0; p < 8; p++) s += g_lowpart[p * HID + j];
    g_lowrow[j] = s;
}
__global__ void lowfill_kernel(float* __restrict__ out)
{
    int idx = blockIdx.x * blockDim.x + threadIdx.x;
    if (idx >= WIN * HID) return;
    out[idx] = g_lowrow[idx % HID];
}

// ===========================================================================
// Fast accurate softcap: tanh via MUFU-backed __expf
// ===========================================================================
__device__ __forceinline__ float softcap50(float s)
{
    float x = __fdiv_rn(s * SCALEF, 50.0f);
    x = fminf(fmaxf(x, -15.0f), 15.0f);
    float e = __expf(2.0f * x);
    return 50.0f * __fdiv_rn(e - 1.0f, e + 1.0f);
}

// ===========================================================================
// Tensor-core flash attention (q >= 2048), pipelined, all 1-term fp16.
// SMEM map (bytes):
//   Q16 0 (64x528=33792)                    [end 33792]
//   K   33792 (32x528=16896)                [end 50688]
//   VT0 50688 (256x80) VT1 71168            [end 91648]
//   SS  91648 (64x36x4=9216)                [end 100864]
//   P16 100864 (64x80=5120)                 [end 105984]
//   m 105984  l 106240  c 106496            [total 106752]
// -> two CTAs per SM: grid (32,8)=256 blocks is ~one wave on 148 SMs.
// ===========================================================================
__global__ __launch_bounds__(256) void flash_mma(
    const __half* __restrict__ Q16,
    const __half* __restrict__ K16,
    const __half* __restrict__ Vt16,
    __half* __restrict__ O16)
{
    extern __shared__ char dsm[];
    const uint32_t sb = smem_u32(dsm);
    float* SS  = (float*)(dsm + 91648);
    float* m_s = (float*)(dsm + 105984);
    float* l_s = (float*)(dsm + 106240);
    float* c_s = (float*)(dsm + 106496);

    const int tid  = threadIdx.x;
    const int warp = tid >> 5;
    const int lane = tid & 31;
    const int h    = blockIdx.y;
    const int hkv  = h >> 1;
    const int it   = 31 - (int)blockIdx.x;
    const int q0r  = it * 64;
    const int nk   = 2 * it + 2;

    const size_t vtbase_g = (size_t)hkv * DH * WIN;

    // prologue: Q, K(0), VT(0)
#pragma unroll
    for (int i = 0; i < 8; i++) {
        int c = tid + (i << 8);                // 0..2047
        int row = c >> 5, ch = c & 31;
        uint32_t dst = sb + (uint32_t)(row * 528 + ch * 16);
        const char* src = (const char*)(Q16 + (size_t)(q0r + row) * QDIM + h * DH) + ch * 16;
        CP_ASYNC16(dst, src);
    }
#pragma unroll
    for (int i = 0; i < 4; i++) {
        int c = tid + (i << 8);
        int row = c >> 5, ch = c & 31;
        uint32_t dst = sb + 33792u + (uint32_t)(row * 528 + ch * 16);
        const char* src = (const char*)(K16 + (size_t)row * KDIM + hkv * DH) + ch * 16;
        CP_ASYNC16(dst, src);
    }
#pragma unroll
    for (int i = 0; i < 4; i++) {
        int c = tid + (i << 8);
        int row = c >> 2, ch = c & 3;
        uint32_t dst = sb + 50688u + (uint32_t)(row * 80 + ch * 16);
        const char* src = (const char*)(Vt16 + vtbase_g + (size_t)row * WIN) + ch * 16;
        CP_ASYNC16(dst, src);
    }
    CP_COMMIT();

    if (tid < 64) { m_s[tid] = -INFINITY; l_s[tid] = 0.0f; }

    float o[4][4][4];
#pragma unroll
    for (int a = 0; a < 4; a++)
#pragma unroll
        for (int b = 0; b < 4; b++)
#pragma unroll
            for (int c = 0; c < 4; c++) o[a][b][c] = 0.0f;

    const int wm = warp >> 1;
    const int wn = warp & 1;
    const int qr = lane >> 2, qc = (lane & 3) * 2;

    for (int t = 0; t < nk; t++) {
        if (t + 1 < nk) {
            const int k1 = (t + 1) * 32;
            const uint32_t vtoff = 50688u + (uint32_t)(((t + 1) & 1) * 20480);
#pragma unroll
            for (int i = 0; i < 4; i++) {
                int c = tid + (i << 8);
                int row = c >> 2, ch = c & 3;
                uint32_t dst = sb + vtoff + (uint32_t)(row * 80 + ch * 16);
                const char* src = (const char*)(Vt16 + vtbase_g + (size_t)row * WIN + k1) + ch * 16;
                CP_ASYNC16(dst, src);
            }
            CP_COMMIT();
            CP_WAIT1();
        } else {
            CP_WAIT0();
        }
        __syncthreads();

        const int k0r = t * 32;

        // ---- QK^T: 1-term ----
        float s[2][4];
#pragma unroll
        for (int nf = 0; nf < 2; nf++)
#pragma unroll
            for (int e = 0; e < 4; e++) s[nf][e] = 0.0f;

#pragma unroll
        for (int ds = 0; ds < 16; ds++) {
            uint32_t aq[4], kh4[4];
            uint32_t qa = sb + (uint32_t)((wm * 16 + (lane & 15)) * 528
                           + ds * 32 + ((lane >> 4) << 4));
            LDSM4(aq, qa);
            uint32_t ka = sb + 33792u + (uint32_t)((wn * 16 + (lane & 15)) * 528
                           + ds * 32 + ((lane >> 4) << 4));
            LDSM4(kh4, ka);
            uint32_t bh0[2] = {kh4[0], kh4[2]}, bh1[2] = {kh4[1], kh4[3]};
            MMA16(s[0], aq, bh0);
            MMA16(s[1], aq, bh1);
        }

#pragma unroll
        for (int nf = 0; nf < 2; nf++)
#pragma unroll
            for (int e = 0; e < 4; e++) {
                int r = wm * 16 + qr + ((e >> 1) * 8);
                int cI = wn * 16 + nf * 8 + qc + (e & 1);
                float v = softcap50(s[nf][e]);
                if (k0r + cI > q0r + r) v = NEGC;
                SS[r * 36 + cI] = v;
            }
        __syncthreads();

        // issue K(t+1)
        if (t + 1 < nk) {
            const int k1 = (t + 1) * 32;
#pragma unroll
            for (int i = 0; i < 4; i++) {
                int c = tid + (i << 8);
                int row = c >> 5, ch = c & 31;
                uint32_t dst = sb + 33792u + (uint32_t)(row * 528 + ch * 16);
                const char* src = (const char*)(K16 + (size_t)(k1 + row) * KDIM + hkv * DH) + ch * 16;
                CP_ASYNC16(dst, src);
            }
            CP_COMMIT();
        }

        // ---- parallel softmax, P single-rounded fp16 ----
        {
            int r = tid >> 2, sub = tid & 3;
            const float* rp = SS + r * 36 + sub * 8;
            float mo = m_s[r];
            float v[8];
#pragma unroll
            for (int j = 0; j < 8; j++) v[j] = rp[j];
            float mx8 = v[0];
#pragma unroll
            for (int j = 1; j < 8; j++) mx8 = fmaxf(mx8, v[j]);
            mx8 = fmaxf(mx8, __shfl_xor_sync(0xFFFFFFFFu, mx8, 1));
            mx8 = fmaxf(mx8, __shfl_xor_sync(0xFFFFFFFFu, mx8, 2));
            float mx = fmaxf(mo, mx8);
            float corr = expf(mo - mx);
            __half* ph = (__half*)(dsm + 100864) + r * 40 + sub * 8;
            float sum = 0.0f;
#pragma unroll
            for (int j = 0; j < 8; j++) {
                float p = expf(v[j] - mx);
                sum += p;
                ph[j] = __float2half_rn(p);
            }
            sum += __shfl_xor_sync(0xFFFFFFFFu, sum, 1);
            sum += __shfl_xor_sync(0xFFFFFFFFu, sum, 2);
            if (sub == 0) {
                m_s[r] = mx;
                l_s[r] = fmaf(l_s[r], corr, sum);
                c_s[r] = corr;
            }
        }
        __syncthreads();

        // ---- rescale O ----
#pragma unroll
        for (int mf = 0; mf < 4; mf++) {
            float c0 = c_s[mf * 16 + qr];
            float c1 = c_s[mf * 16 + qr + 8];
#pragma unroll
            for (int nf = 0; nf < 4; nf++) {
                o[mf][nf][0] *= c0; o[mf][nf][1] *= c0;
                o[mf][nf][2] *= c1; o[mf][nf][3] *= c1;
            }
        }

        // ---- PV: 1-term ----
        const uint32_t vtb = sb + 50688u + (uint32_t)((t & 1) * 20480);
#pragma unroll
        for (int ks = 0; ks < 2; ks++) {
            uint32_t ap[4][4], bh[4][2];
#pragma unroll
            for (int mf = 0; mf < 4; mf++) {
                uint32_t pa = sb + 100864u + (uint32_t)((mf * 16 + (lane & 15)) * 80
                               + ks * 32 + ((lane >> 4) << 4));
                LDSM4(ap[mf], pa);
            }
#pragma unroll
            for (int g = 0; g < 2; g++) {
                uint32_t va = vtb + (uint32_t)((warp * 32 + g * 16 + (lane & 15)) * 80
                               + ks * 32 + ((lane >> 4) << 4));
                uint32_t vh4[4];
                LDSM4(vh4, va);
                bh[2 * g][0]     = vh4[0]; bh[2 * g][1]     = vh4[2];
                bh[2 * g + 1][0] = vh4[1]; bh[2 * g + 1][1] = vh4[3];
            }
#pragma unroll
            for (int mf = 0; mf < 4; mf++)
#pragma unroll
                for (int nf = 0; nf < 4; nf++)
                    MMA16(o[mf][nf], ap[mf], bh[nf]);
        }
        __syncthreads();
    }

    // epilogue: single-rounded fp16 output
#pragma unroll
    for (int mf = 0; mf < 4; mf++) {
        float li0 = l_s[mf * 16 + qr];
        float li1 = l_s[mf * 16 + qr + 8];
        int r0 = q0r + mf * 16 + qr;
#pragma unroll
        for (int nf = 0; nf < 4; nf++) {
            int dcol = warp * 32 + nf * 8 + qc;
            size_t o0 = (size_t)r0 * QDIM + h * DH + dcol;
            size_t o1 = (size_t)(r0 + 8) * QDIM + h * DH + dcol;
            *(__half2*)(O16 + o0) = __halves2half2(
                __float2half_rn(__fdiv_rn(o[mf][nf][0], li0)),
                __float2half_rn(__fdiv_rn(o[mf][nf][1], li0)));
            *(__half2*)(O16 + o1) = __halves2half2(
                __float2half_rn(__fdiv_rn(o[mf][nf][2], li1)),
                __float2half_rn(__fdiv_rn(o[mf][nf][3], li1)));
        }
    }
}

// ===========================================================================
extern "C" void kernel_launch(void* const* d_in, const int* in_sizes, int n_in,
                              void* d_out, int out_size)
{
    const float* x  = (const float*)d_in[0];
    const float* wq = (const float*)d_in[2];
    const float* wk = (const float*)d_in[3];
    const float* wv = (const float*)d_in[4];
    const float* wo = (const float*)d_in[5];
    float* out = (float*)d_out;

    float* pqkv;
    cudaGetSymbolAddress((void**)&pqkv, g_qkv);
    __half *x16, *a16, *q16, *k16, *vt16, *wqkv16, *wo16;
    cudaGetSymbolAddress((void**)&x16,    g_x16);
    cudaGetSymbolAddress((void**)&a16,    g_a16);
    cudaGetSymbolAddress((void**)&q16,    g_q16);
    cudaGetSymbolAddress((void**)&k16,    g_k16);
    cudaGetSymbolAddress((void**)&vt16,   g_vt16);
    cudaGetSymbolAddress((void**)&wqkv16, g_wqkv16);
    cudaGetSymbolAddress((void**)&wo16,   g_wo16);

    dim3 blk(256);
    dim3 tb(32, 8);
    const int GEMM_SMEM  = 40960;
    const int FLASH_SMEM = 106752;
    cudaFuncSetAttribute(gemm_mma1, cudaFuncAttributeMaxDynamicSharedMemorySize, GEMM_SMEM);
    cudaFuncSetAttribute(flash_mma, cudaFuncAttributeMaxDynamicSharedMemorySize, FLASH_SMEM);

    // index 3 = fused QKV gemm (ncu capture slot)
    {
        int n4 = WIN * HID / 4;
        cvt16_kernel<<<(n4 + 255) / 256, blk>>>(x + (size_t)WIN * HID, x16, n4);  // 0
    }
    splitT_qkv_kernel<<<dim3(QKVN / 32, HID / 32), tb>>>(wq, wk, wv);          // 1
    splitT_wo_kernel<<<dim3(HID / 32, QDIM / 32), tb>>>(wo);                   // 2
    gemm_mma1<<<dim3(QKVN / 128, WIN / 128), blk, GEMM_SMEM>>>(                // 3
        x16, wqkv16, pqkv, WIN, QKVN, HID);

    // RoPE + operand prep (all single-rounded fp16)
    invf_init_kernel<<<1, 128>>>();
    rope_cvt_kernel<<<WIN, 128>>>(0, NHQ, q16);
    rope_cvt_kernel<<<WIN, 128>>>(QDIM, NKV, k16);
    vt_split_kernel<<<dim3(WIN / 32, DH / 32, NKV), tb>>>();

    // lowq rows: xsum -> vmean -> lowrow -> fill (full fp32, exact)
    xsum_part_kernel<<<dim3(9, 16), blk>>>(x);
    xsum_comb_kernel<<<9, blk>>>();
    vmean_part_kernel<<<dim3(4, 8), blk>>>(wv);
    vmean_comb_kernel<<<4, blk>>>();
    lowout_part_kernel<<<dim3(9, 8), blk>>>(wo);
    lowout_comb_kernel<<<9, blk>>>();
    lowfill_kernel<<<(WIN * HID + 255) / 256, blk>>>(out);

    // Flash attention (q >= 2048); 1-term fp16, 2 CTAs/SM
    flash_mma<<<dim3(32, NHQ), blk, FLASH_SMEM>>>(q16, k16, vt16, a16);

    // Output projection: 1-term
    gemm_mma1<<<dim3(HID / 128, WIN / 128), blk, GEMM_SMEM>>>(
        a16, wo16, out + (size_t)WIN * HID, WIN, HID, QDIM);
}